// round 10
// baseline (speedup 1.0000x reference)
#include <cuda_runtime.h>
#include <cstdint>

#define N_TOK    8192
#define M_DIM    2048
#define E_NUM    8
#define H_DIM    8192
#define C_CAP    1024
#define EC_SLOTS 8192

#define KCHUNK   64
#define ROW_B    80
#define A_PLANE  (128 * ROW_B)
#define B_PLANE  (64 * ROW_B)
#define STAGE_B  (2 * A_PLANE + 2 * B_PLANE)
#define NSTAGE   5
#define SMEM_BYTES (NSTAGE * STAGE_B)
#define NTHREADS 512
#define QMAX 32512.0f

__device__ int    g_idx  [N_TOK];
__device__ float  g_gate1[N_TOK];
__device__ float  g_gates[N_TOK * E_NUM];
__device__ int    g_s2t  [EC_SLOTS];

__device__ char   g_xA1[(size_t)EC_SLOTS * M_DIM];
__device__ char   g_xA2[(size_t)EC_SLOTS * M_DIM];
__device__ float  g_sax[EC_SLOTS];
__device__ float  g_hf [(size_t)EC_SLOTS * H_DIM];
__device__ char   g_hA1[(size_t)EC_SLOTS * H_DIM];
__device__ char   g_hA2[(size_t)EC_SLOTS * H_DIM];
__device__ float  g_sah[EC_SLOTS];
__device__ char   g_w1B1[(size_t)E_NUM * H_DIM * M_DIM];
__device__ char   g_w1B2[(size_t)E_NUM * H_DIM * M_DIM];
__device__ float  g_sw1[(size_t)E_NUM * H_DIM];
__device__ char   g_w2B1[(size_t)E_NUM * M_DIM * H_DIM];
__device__ char   g_w2B2[(size_t)E_NUM * M_DIM * H_DIM];
__device__ float  g_sw2[(size_t)E_NUM * M_DIM];

__device__ __forceinline__ uint32_t s2u(const void* p) {
    return (uint32_t)__cvta_generic_to_shared(p);
}
__device__ __forceinline__ void cp16(uint32_t s, const void* g) {
    asm volatile("cp.async.cg.shared.global [%0], [%1], 16;" :: "r"(s), "l"(g));
}
__device__ __forceinline__ void ldsm4(uint32_t* r, uint32_t a) {
    asm volatile("ldmatrix.sync.aligned.m8n8.x4.shared.b16 {%0,%1,%2,%3}, [%4];"
                 : "=r"(r[0]), "=r"(r[1]), "=r"(r[2]), "=r"(r[3]) : "r"(a));
}
__device__ __forceinline__ void ldsm2(uint32_t* r, uint32_t a) {
    asm volatile("ldmatrix.sync.aligned.m8n8.x2.shared.b16 {%0,%1}, [%2];"
                 : "=r"(r[0]), "=r"(r[1]) : "r"(a));
}
__device__ __forceinline__ void immas8(int* d, const uint32_t* a, const uint32_t* b) {
    asm volatile("mma.sync.aligned.m16n8k32.row.col.s32.s8.s8.s32 "
                 "{%0,%1,%2,%3}, {%4,%5,%6,%7}, {%8,%9}, {%0,%1,%2,%3};"
                 : "+r"(d[0]), "+r"(d[1]), "+r"(d[2]), "+r"(d[3])
                 : "r"(a[0]), "r"(a[1]), "r"(a[2]), "r"(a[3]),
                   "r"(b[0]), "r"(b[1]));
}
__device__ __forceinline__ void qsplit(float q, char& c1, char& c2) {
    float f1 = rintf(q * (1.0f / 256.0f));
    float f2 = q - 256.0f * f1;
    if (f2 > 127.0f)  { f2 -= 256.0f; f1 += 1.0f; }
    if (f2 < -128.0f) { f2 += 256.0f; f1 -= 1.0f; }
    c1 = (char)(int)f1;
    c2 = (char)(int)f2;
}
__device__ __forceinline__ float qcombine(int hi, int mid, int lo) {
    return fmaf(65536.f, __int2float_rn(hi),
                fmaf(256.f, __int2float_rn(mid), __int2float_rn(lo)));
}

// ---------------- init ----------------
__global__ void init_kernel(float* __restrict__ out)
{
    int tid = blockIdx.x * blockDim.x + threadIdx.x;
    if (tid < EC_SLOTS) g_s2t[tid] = -1;
    float4* o4 = (float4*)out;
    const int n4 = (N_TOK * M_DIM) / 4;
    const int stride = gridDim.x * blockDim.x;
    for (int i = tid; i < n4; i += stride)
        o4[i] = make_float4(0.f, 0.f, 0.f, 0.f);
}

// ---------------- gate: exact fp32 routing ----------------
__global__ __launch_bounds__(256) void gate_kernel(
    const float* __restrict__ x, const float* __restrict__ wg)
{
    __shared__ float sx[M_DIM];
    __shared__ float slog[E_NUM];
    const int tok = blockIdx.x, tid = threadIdx.x;

    const float4* xr = (const float4*)(x + (size_t)tok * M_DIM);
    float4* sx4 = (float4*)sx;
    for (int i = tid; i < M_DIM / 4; i += 256) sx4[i] = xr[i];
    __syncthreads();

    const int wid = tid >> 5, lane = tid & 31;
    const float* __restrict__ w = wg + wid * M_DIM;
    float sum = 0.f;
    for (int m = lane; m < M_DIM; m += 32) sum = fmaf(sx[m], w[m], sum);
#pragma unroll
    for (int o = 16; o; o >>= 1) sum += __shfl_xor_sync(0xffffffffu, sum, o);
    if (lane == 0) slog[wid] = sum;
    __syncthreads();

    if (tid == 0) {
        float mx = slog[0]; int am = 0;
#pragma unroll
        for (int e = 1; e < E_NUM; ++e)
            if (slog[e] > mx) { mx = slog[e]; am = e; }
        float ge[E_NUM], den = 0.f;
#pragma unroll
        for (int e = 0; e < E_NUM; ++e) { ge[e] = expf(slog[e] - mx); den += ge[e]; }
        const float inv = 1.f / den;
#pragma unroll
        for (int e = 0; e < E_NUM; ++e) g_gates[tok * E_NUM + e] = ge[e] * inv;
        g_idx[tok]   = am;
        g_gate1[tok] = ge[am] * inv;
    }
}

// ---------------- sched: exact cumsum capacity + l_aux ----------------
__global__ __launch_bounds__(256) void sched_kernel(float* __restrict__ out,
                                                    int write_laux)
{
    __shared__ int   s_ce[E_NUM];
    __shared__ float s_me[E_NUM];
    const int tid = threadIdx.x;
    const int wid = tid >> 5, lane = tid & 31;

    int count = 0;
    for (int base = 0; base < N_TOK; base += 32) {
        const int tok = base + lane;
        const bool mine = (g_idx[tok] == wid);
        const unsigned bal = __ballot_sync(0xffffffffu, mine);
        if (mine) {
            const int loc = count + __popc(bal & ((1u << lane) - 1u));
            if (loc < C_CAP) g_s2t[wid * C_CAP + loc] = tok;
        }
        count += __popc(bal);
    }
    if (lane == 0) s_ce[wid] = count;

    float me = 0.f;
    for (int t = lane; t < N_TOK; t += 32) me += g_gates[t * E_NUM + wid];
#pragma unroll
    for (int o = 16; o; o >>= 1) me += __shfl_xor_sync(0xffffffffu, me, o);
    if (lane == 0) s_me[wid] = me;
    __syncthreads();

    if (tid == 0 && write_laux) {
        float acc = 0.f;
#pragma unroll
        for (int e = 0; e < E_NUM; ++e) acc += s_me[e] * (float)s_ce[e];
        out[(size_t)N_TOK * M_DIM] =
            acc * ((float)E_NUM / ((float)N_TOK * (float)N_TOK));
    }
}

// ---------------- rowquant: row max + 2-plane int8 quantize ----------------
template<int KD>
__global__ __launch_bounds__(256) void rowquant_kernel(
    const float* __restrict__ src, int use_s2t,
    char* __restrict__ p1, char* __restrict__ p2, float* __restrict__ sc)
{
    __shared__ float smax[8];
    const int slot = blockIdx.x, tid = threadIdx.x;
    int t = use_s2t ? g_s2t[slot] : slot;
    const float4* row = (t >= 0) ? (const float4*)(src + (size_t)t * KD) : nullptr;

    float m = 0.f;
    if (row)
        for (int i = tid; i < KD / 4; i += 256) {
            float4 v = row[i];
            m = fmaxf(m, fmaxf(fmaxf(fabsf(v.x), fabsf(v.y)),
                               fmaxf(fabsf(v.z), fabsf(v.w))));
        }
#pragma unroll
    for (int o = 16; o; o >>= 1) m = fmaxf(m, __shfl_xor_sync(0xffffffffu, m, o));
    if ((tid & 31) == 0) smax[tid >> 5] = m;
    __syncthreads();
    if (tid < 8) {
        float v = smax[tid];
#pragma unroll
        for (int o = 4; o; o >>= 1) v = fmaxf(v, __shfl_xor_sync(0xffu, v, o));
        if (tid == 0) smax[0] = fmaxf(v, 1e-30f);
    }
    __syncthreads();
    const float mx = smax[0];
    const float inv = QMAX / mx;
    if (tid == 0) sc[slot] = mx / QMAX;

    char* d1 = p1 + (size_t)slot * KD;
    char* d2 = p2 + (size_t)slot * KD;
    for (int i = tid; i < KD / 4; i += 256) {
        char c1[4] = {0,0,0,0}, c2[4] = {0,0,0,0};
        if (row) {
            float4 v = row[i];
            qsplit(rintf(v.x * inv), c1[0], c2[0]);
            qsplit(rintf(v.y * inv), c1[1], c2[1]);
            qsplit(rintf(v.z * inv), c1[2], c2[2]);
            qsplit(rintf(v.w * inv), c1[3], c2[3]);
        }
        *(uint32_t*)(d1 + i * 4) = *(uint32_t*)c1;
        *(uint32_t*)(d2 + i * 4) = *(uint32_t*)c2;
    }
}

// ---------------- colmax: per (e,c) scale ----------------
__global__ void colmax_kernel(const float* __restrict__ src,
                              float* __restrict__ sc, int R, int C)
{
    const int e = blockIdx.y;
    const int c = blockIdx.x * 256 + threadIdx.x;
    const float* s = src + (size_t)e * R * C + c;
    float m = 0.f;
    for (int r = 0; r < R; ++r) m = fmaxf(m, fabsf(s[(size_t)r * C]));
    sc[(size_t)e * C + c] = fmaxf(m, 1e-30f) / QMAX;
}

// ---------------- wquant: transpose + 2-plane quantize ----------------
__global__ void wquant_kernel(const float* __restrict__ src,
                              const float* __restrict__ sc,
                              char* __restrict__ p1, char* __restrict__ p2,
                              int R, int C)
{
    __shared__ float tile[32][33];
    __shared__ float sinv[32];
    const int e  = blockIdx.z;
    const int c0 = blockIdx.x * 32;
    const int r0 = blockIdx.y * 32;
    const int tx = threadIdx.x, ty = threadIdx.y;

    const float* s = src + (size_t)e * R * C;
#pragma unroll
    for (int i = 0; i < 4; ++i)
        tile[ty + 8 * i][tx] = s[(size_t)(r0 + ty + 8 * i) * C + c0 + tx];
    if (ty == 0) sinv[tx] = 1.0f / sc[(size_t)e * C + c0 + tx];
    __syncthreads();

    char* d1 = p1 + (size_t)e * C * R;
    char* d2 = p2 + (size_t)e * C * R;
#pragma unroll
    for (int i = 0; i < 4; ++i) {
        const int c = c0 + ty + 8 * i;
        const int r = r0 + tx;
        char c1, c2;
        qsplit(rintf(tile[tx][ty + 8 * i] * sinv[ty + 8 * i]), c1, c2);
        d1[(size_t)c * R + r] = c1;
        d2[(size_t)c * R + r] = c2;
    }
}

// ---------------- IMMA mainloop: 3 acc streams, 5-stage pipeline ----------------
__device__ __forceinline__ void imma_mainloop(
    const char* __restrict__ A1, const char* __restrict__ A2,
    const char* __restrict__ B1, const char* __restrict__ B2,
    size_t pitch, int chunks, char* smem,
    int ahi[2][2][4], int amid[2][2][4], int alo[2][2][4])
{
    const int tid  = threadIdx.x;
    const int wid  = tid >> 5, lane = tid & 31;
    const int wm   = (wid & 3) * 32;
    const int wn   = (wid >> 2) * 16;
    const uint32_t sbase = s2u(smem);

    const int arow = tid >> 2, aseg = tid & 3;
    const uint32_t aso = arow * ROW_B + aseg * 16;
    const int bsel = tid >> 8;
    const int brow = (tid & 255) >> 2, bseg = tid & 3;
    const uint32_t bso = brow * ROW_B + bseg * 16;

    auto load_stage = [&](int st, int c) {
        const uint32_t sb = sbase + st * STAGE_B;
        const size_t ka = (size_t)arow * pitch + (size_t)c * KCHUNK + aseg * 16;
        cp16(sb + aso,           A1 + ka);
        cp16(sb + A_PLANE + aso, A2 + ka);
        const size_t kb = (size_t)brow * pitch + (size_t)c * KCHUNK + bseg * 16;
        cp16(sb + 2 * A_PLANE + bsel * B_PLANE + bso, (bsel ? B2 : B1) + kb);
        asm volatile("cp.async.commit_group;");
    };

#pragma unroll
    for (int s = 0; s < NSTAGE - 1; ++s) load_stage(s, s);

    const uint32_t aoff = (uint32_t)((wm + (lane & 15)) * ROW_B
                                     + ((lane >> 4) & 1) * 16);
    const uint32_t boff = (uint32_t)((wn + (lane & 7)) * ROW_B
                                     + ((lane >> 3) & 1) * 16);

    int buf = 0;
#pragma unroll 1
    for (int c = 0; c < chunks; ++c) {
        asm volatile("cp.async.wait_group %0;" :: "n"(NSTAGE - 2) : "memory");
        __syncthreads();

        if (c + NSTAGE - 1 < chunks)
            load_stage((c + NSTAGE - 1) % NSTAGE, c + NSTAGE - 1);

        const uint32_t sb = sbase + buf * STAGE_B;
#pragma unroll
        for (int ks = 0; ks < 2; ++ks) {
            const int kb = ks * 32;
            uint32_t a1f[2][4], a2f[2][4], b1f[2][2], b2f[2][2];
#pragma unroll
            for (int mi = 0; mi < 2; ++mi) {
                const uint32_t ad = sb + aoff + kb + mi * 16 * ROW_B;
                ldsm4(a1f[mi], ad);
                ldsm4(a2f[mi], ad + A_PLANE);
            }
#pragma unroll
            for (int ni = 0; ni < 2; ++ni) {
                const uint32_t bd = sb + 2 * A_PLANE + boff + kb + ni * 8 * ROW_B;
                ldsm2(b1f[ni], bd);
                ldsm2(b2f[ni], bd + B_PLANE);
            }
#pragma unroll
            for (int mi = 0; mi < 2; ++mi)
#pragma unroll
                for (int ni = 0; ni < 2; ++ni)
                    immas8(ahi[mi][ni], a1f[mi], b1f[ni]);
#pragma unroll
            for (int mi = 0; mi < 2; ++mi)
#pragma unroll
                for (int ni = 0; ni < 2; ++ni)
                    immas8(amid[mi][ni], a1f[mi], b2f[ni]);
#pragma unroll
            for (int mi = 0; mi < 2; ++mi)
#pragma unroll
                for (int ni = 0; ni < 2; ++ni)
                    immas8(amid[mi][ni], a2f[mi], b1f[ni]);
#pragma unroll
            for (int mi = 0; mi < 2; ++mi)
#pragma unroll
                for (int ni = 0; ni < 2; ++ni)
                    immas8(alo[mi][ni], a2f[mi], b2f[ni]);
        }
        buf = (buf + 1 == NSTAGE) ? 0 : buf + 1;
    }
}

#define ACC_DECL \
    int ahi[2][2][4], amid[2][2][4], alo[2][2][4]; \
    _Pragma("unroll") for (int mi = 0; mi < 2; ++mi) \
    _Pragma("unroll") for (int ni = 0; ni < 2; ++ni) \
    _Pragma("unroll") for (int k = 0; k < 4; ++k) { \
        ahi[mi][ni][k] = 0; amid[mi][ni][k] = 0; alo[mi][ni][k] = 0; }

// ---------------- GEMM1: hf = relu(xq @ w1q + b1) ----------------
__global__ __launch_bounds__(NTHREADS, 1) void gemm1_imma(const float* __restrict__ b1)
{
    extern __shared__ char smem[];
    const int tid = threadIdx.x;
    const int wid = tid >> 5, lane = tid & 31;
    const int row0 = blockIdx.y * 128;
    const int col0 = blockIdx.x * 64;
    const int e    = row0 >> 10;

    ACC_DECL;
    imma_mainloop(
        g_xA1 + (size_t)row0 * M_DIM, g_xA2 + (size_t)row0 * M_DIM,
        g_w1B1 + (size_t)e * H_DIM * M_DIM + (size_t)col0 * M_DIM,
        g_w1B2 + (size_t)e * H_DIM * M_DIM + (size_t)col0 * M_DIM,
        (size_t)M_DIM, M_DIM / KCHUNK, smem, ahi, amid, alo);

    const int wm = (wid & 3) * 32;
    const int wn = (wid >> 2) * 16;
    const float* b1g = b1 + (size_t)e * H_DIM;
    const float* swg = g_sw1 + (size_t)e * H_DIM;

#pragma unroll
    for (int mi = 0; mi < 2; ++mi) {
        const int r0 = row0 + wm + 16 * mi + (lane >> 2);
        const float sa0 = g_sax[r0], sa1 = g_sax[r0 + 8];
#pragma unroll
        for (int ni = 0; ni < 2; ++ni) {
            const int cg = col0 + wn + 8 * ni + (lane & 3) * 2;
            const float s0 = swg[cg], s1 = swg[cg + 1];
            const float bb0 = b1g[cg], bb1 = b1g[cg + 1];
            float2 w0, w1;
            w0.x = fmaxf(fmaf(sa0 * s0,
                   qcombine(ahi[mi][ni][0], amid[mi][ni][0], alo[mi][ni][0]), bb0), 0.f);
            w0.y = fmaxf(fmaf(sa0 * s1,
                   qcombine(ahi[mi][ni][1], amid[mi][ni][1], alo[mi][ni][1]), bb1), 0.f);
            w1.x = fmaxf(fmaf(sa1 * s0,
                   qcombine(ahi[mi][ni][2], amid[mi][ni][2], alo[mi][ni][2]), bb0), 0.f);
            w1.y = fmaxf(fmaf(sa1 * s1,
                   qcombine(ahi[mi][ni][3], amid[mi][ni][3], alo[mi][ni][3]), bb1), 0.f);
            *(float2*)(g_hf + (size_t)r0 * H_DIM + cg)       = w0;
            *(float2*)(g_hf + (size_t)(r0 + 8) * H_DIM + cg) = w1;
        }
    }
}

// ---------------- GEMM2: out = gate1 * (hq @ w2q + b2), scatter ----------------
__global__ __launch_bounds__(NTHREADS, 1) void gemm2_imma(const float* __restrict__ b2,
                                                          float* __restrict__ out)
{
    extern __shared__ char smem[];
    const int tid = threadIdx.x;
    const int wid = tid >> 5, lane = tid & 31;
    const int row0 = blockIdx.y * 128;
    const int col0 = blockIdx.x * 64;
    const int e    = row0 >> 10;

    ACC_DECL;
    imma_mainloop(
        g_hA1 + (size_t)row0 * H_DIM, g_hA2 + (size_t)row0 * H_DIM,
        g_w2B1 + (size_t)e * M_DIM * H_DIM + (size_t)col0 * H_DIM,
        g_w2B2 + (size_t)e * M_DIM * H_DIM + (size_t)col0 * H_DIM,
        (size_t)H_DIM, H_DIM / KCHUNK, smem, ahi, amid, alo);

    const int wm = (wid & 3) * 32;
    const int wn = (wid >> 2) * 16;
    const float* b2g = b2 + (size_t)e * M_DIM;
    const float* swg = g_sw2 + (size_t)e * M_DIM;

#pragma unroll
    for (int mi = 0; mi < 2; ++mi) {
#pragma unroll
        for (int h = 0; h < 2; ++h) {
            const int rg = row0 + wm + 16 * mi + (lane >> 2) + 8 * h;
            const int t = g_s2t[rg];
            if (t < 0) continue;
            const float gsa = g_gate1[t];
            const float sa = g_sah[rg];
#pragma unroll
            for (int ni = 0; ni < 2; ++ni) {
                const int cg = col0 + wn + 8 * ni + (lane & 3) * 2;
                float2 v;
                v.x = gsa * fmaf(sa * swg[cg],
                      qcombine(ahi[mi][ni][2*h], amid[mi][ni][2*h], alo[mi][ni][2*h]),
                      b2g[cg]);
                v.y = gsa * fmaf(sa * swg[cg + 1],
                      qcombine(ahi[mi][ni][2*h+1], amid[mi][ni][2*h+1], alo[mi][ni][2*h+1]),
                      b2g[cg + 1]);
                *(float2*)(out + (size_t)t * M_DIM + cg) = v;
            }
        }
    }
}

// ---------------- launch ----------------
extern "C" void kernel_launch(void* const* d_in, const int* in_sizes, int n_in,
                              void* d_out, int out_size)
{
    const float* x  = (const float*)d_in[0];
    const float* wg = (const float*)d_in[1];
    const float* w1 = (const float*)d_in[2];
    const float* b1 = (const float*)d_in[3];
    const float* w2 = (const float*)d_in[4];
    const float* b2 = (const float*)d_in[5];
    float* out = (float*)d_out;

    cudaFuncSetAttribute(gemm1_imma, cudaFuncAttributeMaxDynamicSharedMemorySize,
                         SMEM_BYTES);
    cudaFuncSetAttribute(gemm2_imma, cudaFuncAttributeMaxDynamicSharedMemorySize,
                         SMEM_BYTES);

    char *w1B1, *w1B2, *w2B1, *w2B2, *xA1, *xA2, *hA1, *hA2;
    float *sw1, *sw2, *sax, *sah, *hf;
    cudaGetSymbolAddress((void**)&w1B1, g_w1B1);
    cudaGetSymbolAddress((void**)&w1B2, g_w1B2);
    cudaGetSymbolAddress((void**)&w2B1, g_w2B1);
    cudaGetSymbolAddress((void**)&w2B2, g_w2B2);
    cudaGetSymbolAddress((void**)&sw1, g_sw1);
    cudaGetSymbolAddress((void**)&sw2, g_sw2);
    cudaGetSymbolAddress((void**)&xA1, g_xA1);
    cudaGetSymbolAddress((void**)&xA2, g_xA2);
    cudaGetSymbolAddress((void**)&hA1, g_hA1);
    cudaGetSymbolAddress((void**)&hA2, g_hA2);
    cudaGetSymbolAddress((void**)&sax, g_sax);
    cudaGetSymbolAddress((void**)&sah, g_sah);
    cudaGetSymbolAddress((void**)&hf,  g_hf);

    init_kernel<<<256, 256>>>(out);

    colmax_kernel<<<dim3(H_DIM / 256, E_NUM), 256>>>(w1, sw1, M_DIM, H_DIM);
    colmax_kernel<<<dim3(M_DIM / 256, E_NUM), 256>>>(w2, sw2, H_DIM, M_DIM);
    wquant_kernel<<<dim3(H_DIM / 32, M_DIM / 32, E_NUM), dim3(32, 8)>>>(
        w1, sw1, w1B1, w1B2, M_DIM, H_DIM);
    wquant_kernel<<<dim3(M_DIM / 32, H_DIM / 32, E_NUM), dim3(32, 8)>>>(
        w2, sw2, w2B1, w2B2, H_DIM, M_DIM);

    gate_kernel<<<N_TOK, 256>>>(x, wg);
    sched_kernel<<<1, 256>>>(out, (out_size > N_TOK * M_DIM) ? 1 : 0);
    rowquant_kernel<M_DIM><<<EC_SLOTS, 256>>>(x, 1, xA1, xA2, sax);

    gemm1_imma<<<dim3(H_DIM / 64, EC_SLOTS / 128), NTHREADS, SMEM_BYTES>>>(b1);
    rowquant_kernel<H_DIM><<<EC_SLOTS, 256>>>(hf, 0, hA1, hA2, sah);
    gemm2_imma<<<dim3(M_DIM / 64, EC_SLOTS / 128), NTHREADS, SMEM_BYTES>>>(b2, out);
}

// round 11
// speedup vs baseline: 1.1768x; 1.1768x over previous
#include <cuda_runtime.h>
#include <cuda_bf16.h>
#include <cstdint>

typedef unsigned long long ull;

#define N_TOK    8192
#define M_DIM    2048
#define E_NUM    8
#define H_DIM    8192
#define C_CAP    1024
#define EC_SLOTS 8192

// hybrid block: 128 rows x 128 cols; fma warps 0-7 cols [0,64), tensor 8-15 cols [64,128)
#define KC       32
#define OFF_AF   0                    // fp32 A: 128 x 36 floats (144B rows)
#define OFF_AH   18432                // bf16 A hi: 128 x 80B
#define OFF_AL   28672
#define OFF_BF   38912                // fp32 B: 32 x 68 floats (272B rows)
#define OFF_BH   47616                // bf16 B hi: 64 x 80B
#define OFF_BL   52736
#define STAGE_B  57856
#define NSTAGE   4
#define SMEM_BYTES (NSTAGE * STAGE_B) // 231424
#define NTHREADS 512

__device__ int    g_idx  [N_TOK];
__device__ float  g_gate1[N_TOK];
__device__ float  g_gates[N_TOK * E_NUM];
__device__ int    g_s2t  [EC_SLOTS];

__device__ float         g_dispf  [(size_t)EC_SLOTS * M_DIM];
__device__ __nv_bfloat16 g_disp_hi[(size_t)EC_SLOTS * M_DIM];
__device__ __nv_bfloat16 g_disp_lo[(size_t)EC_SLOTS * M_DIM];
__device__ float         g_hf     [(size_t)EC_SLOTS * H_DIM];
__device__ __nv_bfloat16 g_h_hi   [(size_t)EC_SLOTS * H_DIM];
__device__ __nv_bfloat16 g_h_lo   [(size_t)EC_SLOTS * H_DIM];
__device__ __nv_bfloat16 g_w1t_hi[(size_t)E_NUM * H_DIM * M_DIM];
__device__ __nv_bfloat16 g_w1t_lo[(size_t)E_NUM * H_DIM * M_DIM];
__device__ __nv_bfloat16 g_w2t_hi[(size_t)E_NUM * M_DIM * H_DIM];
__device__ __nv_bfloat16 g_w2t_lo[(size_t)E_NUM * M_DIM * H_DIM];

__device__ __forceinline__ uint32_t s2u(const void* p) {
    return (uint32_t)__cvta_generic_to_shared(p);
}
__device__ __forceinline__ void cp16(uint32_t s, const void* g) {
    asm volatile("cp.async.cg.shared.global [%0], [%1], 16;" :: "r"(s), "l"(g));
}
__device__ __forceinline__ void ldsm4(uint32_t* r, uint32_t a) {
    asm volatile("ldmatrix.sync.aligned.m8n8.x4.shared.b16 {%0,%1,%2,%3}, [%4];"
                 : "=r"(r[0]), "=r"(r[1]), "=r"(r[2]), "=r"(r[3]) : "r"(a));
}
__device__ __forceinline__ void ldsm2(uint32_t* r, uint32_t a) {
    asm volatile("ldmatrix.sync.aligned.m8n8.x2.shared.b16 {%0,%1}, [%2];"
                 : "=r"(r[0]), "=r"(r[1]) : "r"(a));
}
__device__ __forceinline__ void mmabf16(float* d, const uint32_t* a, const uint32_t* b) {
    asm volatile("mma.sync.aligned.m16n8k16.row.col.f32.bf16.bf16.f32 "
                 "{%0,%1,%2,%3}, {%4,%5,%6,%7}, {%8,%9}, {%0,%1,%2,%3};"
                 : "+f"(d[0]), "+f"(d[1]), "+f"(d[2]), "+f"(d[3])
                 : "r"(a[0]), "r"(a[1]), "r"(a[2]), "r"(a[3]),
                   "r"(b[0]), "r"(b[1]));
}
__device__ __forceinline__ ull f2_fma(ull a, ull b, ull c) {
    ull d;
    asm("fma.rn.f32x2 %0, %1, %2, %3;" : "=l"(d) : "l"(a), "l"(b), "l"(c));
    return d;
}
__device__ __forceinline__ ull pack2(float lo, float hi) {
    ull d;
    asm("mov.b64 %0, {%1, %2};" : "=l"(d) : "f"(lo), "f"(hi));
    return d;
}
__device__ __forceinline__ float2 unpack2(ull v) {
    float2 r;
    asm("mov.b64 {%0, %1}, %2;" : "=f"(r.x), "=f"(r.y) : "l"(v));
    return r;
}
__device__ __forceinline__ void bsplit(float f, __nv_bfloat16& hi, __nv_bfloat16& lo) {
    hi = __float2bfloat16(f);
    lo = __float2bfloat16(f - __bfloat162float(hi));
}

// ---------------- init ----------------
__global__ void init_kernel(float* __restrict__ out)
{
    int tid = blockIdx.x * blockDim.x + threadIdx.x;
    if (tid < EC_SLOTS) g_s2t[tid] = -1;
    float4* o4 = (float4*)out;
    const int n4 = (N_TOK * M_DIM) / 4;
    const int stride = gridDim.x * blockDim.x;
    for (int i = tid; i < n4; i += stride)
        o4[i] = make_float4(0.f, 0.f, 0.f, 0.f);
}

// ---------------- gate ----------------
__global__ __launch_bounds__(256) void gate_kernel(
    const float* __restrict__ x, const float* __restrict__ wg)
{
    __shared__ float sx[M_DIM];
    __shared__ float slog[E_NUM];
    const int tok = blockIdx.x, tid = threadIdx.x;

    const float4* xr = (const float4*)(x + (size_t)tok * M_DIM);
    float4* sx4 = (float4*)sx;
    for (int i = tid; i < M_DIM / 4; i += 256) sx4[i] = xr[i];
    __syncthreads();

    const int wid = tid >> 5, lane = tid & 31;
    const float* __restrict__ w = wg + wid * M_DIM;
    float sum = 0.f;
    for (int m = lane; m < M_DIM; m += 32) sum = fmaf(sx[m], w[m], sum);
#pragma unroll
    for (int o = 16; o; o >>= 1) sum += __shfl_xor_sync(0xffffffffu, sum, o);
    if (lane == 0) slog[wid] = sum;
    __syncthreads();

    if (tid == 0) {
        float mx = slog[0]; int am = 0;
#pragma unroll
        for (int e = 1; e < E_NUM; ++e)
            if (slog[e] > mx) { mx = slog[e]; am = e; }
        float ge[E_NUM], den = 0.f;
#pragma unroll
        for (int e = 0; e < E_NUM; ++e) { ge[e] = expf(slog[e] - mx); den += ge[e]; }
        const float inv = 1.f / den;
#pragma unroll
        for (int e = 0; e < E_NUM; ++e) g_gates[tok * E_NUM + e] = ge[e] * inv;
        g_idx[tok]   = am;
        g_gate1[tok] = ge[am] * inv;
    }
}

// ---------------- sched ----------------
__global__ __launch_bounds__(256) void sched_kernel(float* __restrict__ out,
                                                    int write_laux)
{
    __shared__ int   s_ce[E_NUM];
    __shared__ float s_me[E_NUM];
    const int tid = threadIdx.x;
    const int wid = tid >> 5, lane = tid & 31;

    int count = 0;
    for (int base = 0; base < N_TOK; base += 32) {
        const int tok = base + lane;
        const bool mine = (g_idx[tok] == wid);
        const unsigned bal = __ballot_sync(0xffffffffu, mine);
        if (mine) {
            const int loc = count + __popc(bal & ((1u << lane) - 1u));
            if (loc < C_CAP) g_s2t[wid * C_CAP + loc] = tok;
        }
        count += __popc(bal);
    }
    if (lane == 0) s_ce[wid] = count;

    float me = 0.f;
    for (int t = lane; t < N_TOK; t += 32) me += g_gates[t * E_NUM + wid];
#pragma unroll
    for (int o = 16; o; o >>= 1) me += __shfl_xor_sync(0xffffffffu, me, o);
    if (lane == 0) s_me[wid] = me;
    __syncthreads();

    if (tid == 0 && write_laux) {
        float acc = 0.f;
#pragma unroll
        for (int e = 0; e < E_NUM; ++e) acc += s_me[e] * (float)s_ce[e];
        out[(size_t)N_TOK * M_DIM] =
            acc * ((float)E_NUM / ((float)N_TOK * (float)N_TOK));
    }
}

// ---------------- disp: gather rows -> fp32 + bf16 hi/lo ----------------
__global__ __launch_bounds__(256) void disp_kernel(const float* __restrict__ x)
{
    const int slot = blockIdx.x;
    const int t = g_s2t[slot];
    const float4* src = (t >= 0) ? (const float4*)(x + (size_t)t * M_DIM) : nullptr;
    float4*        df = (float4*)(g_dispf + (size_t)slot * M_DIM);
    __nv_bfloat16* dh = g_disp_hi + (size_t)slot * M_DIM;
    __nv_bfloat16* dl = g_disp_lo + (size_t)slot * M_DIM;
    for (int i = threadIdx.x; i < M_DIM / 4; i += 256) {
        float4 v = src ? src[i] : make_float4(0.f, 0.f, 0.f, 0.f);
        df[i] = v;
        __nv_bfloat16 hh[4], ll[4];
        bsplit(v.x, hh[0], ll[0]); bsplit(v.y, hh[1], ll[1]);
        bsplit(v.z, hh[2], ll[2]); bsplit(v.w, hh[3], ll[3]);
        *(uint2*)(dh + i * 4) = *(uint2*)hh;
        *(uint2*)(dl + i * 4) = *(uint2*)ll;
    }
}

// ---------------- wsplit: bf16 planes, tensor-half columns only ----------------
// maps blockIdx.x to col groups with (c0 mod 128) in {64, 96}
__global__ void wsplit_kernel(const float* __restrict__ src,
                              __nv_bfloat16* __restrict__ dhi,
                              __nv_bfloat16* __restrict__ dlo,
                              int R, int C)
{
    __shared__ float tile[32][33];
    const int e  = blockIdx.z;
    const int bx = blockIdx.x;
    const int c0 = (bx >> 1) * 128 + 64 + (bx & 1) * 32;
    const int r0 = blockIdx.y * 32;
    const int tx = threadIdx.x, ty = threadIdx.y;

    const float* s = src + (size_t)e * R * C;
#pragma unroll
    for (int i = 0; i < 4; ++i)
        tile[ty + 8 * i][tx] = s[(size_t)(r0 + ty + 8 * i) * C + c0 + tx];
    __syncthreads();

    __nv_bfloat16* dh = dhi + (size_t)e * C * R;
    __nv_bfloat16* dl = dlo + (size_t)e * C * R;
#pragma unroll
    for (int i = 0; i < 4; ++i) {
        const int c = c0 + ty + 8 * i;
        const int r = r0 + tx;
        __nv_bfloat16 hi, lo;
        bsplit(tile[tx][ty + 8 * i], hi, lo);
        dh[(size_t)c * R + r] = hi;
        dl[(size_t)c * R + r] = lo;
    }
}

// ---------------- hybrid mainloop ----------------
// A fp32 row-major (pitchA4 bytes), A bf16 hi/lo (pitchA2), B fp32 k-rows
// (pitchBf), B bf16 hi/lo n-rows K-major (pitchA2-equivalent pitchB2).
__device__ __forceinline__ void hybrid_mainloop(
    const char* Af, const char* Ah, const char* Al,
    const char* Bf, size_t pitchBf,
    const char* Bh, const char* Bl, size_t pitchB2,
    size_t pitchA4, size_t pitchA2, int chunks, char* smem,
    ull accf[8][4], float acct[2][4][4])
{
    const int tid  = threadIdx.x;
    const int wid  = tid >> 5, lane = tid & 31;
    const uint32_t sbase = s2u(smem);

    // loader decomposition (6 cp16/thread/stage)
    const int ar = tid >> 3, as = tid & 7;           // Af unit t: r=t>>3 seg=t&7 (u<1024: two)
    const int ar2 = (tid + 512) >> 3, as2 = (tid + 512) & 7;
    const int hr = tid >> 2, hs = tid & 3;           // Ah/Al
    const int bk = tid >> 4, bs = tid & 15;          // Bf
    const int tsel = tid >> 8;                        // 0 -> Bh, 1 -> Bl
    const int tr = (tid & 255) >> 2, ts = tid & 3;

    auto load_stage = [&](int st, int c) {
        const uint32_t sb = sbase + st * STAGE_B;
        const size_t kc4 = (size_t)c * (KC * 4);
        const size_t kc2 = (size_t)c * (KC * 2);
        cp16(sb + OFF_AF + ar * 144 + as * 16,
             Af + (size_t)ar * pitchA4 + kc4 + as * 16);
        cp16(sb + OFF_AF + ar2 * 144 + as2 * 16,
             Af + (size_t)ar2 * pitchA4 + kc4 + as2 * 16);
        cp16(sb + OFF_AH + hr * 80 + hs * 16,
             Ah + (size_t)hr * pitchA2 + kc2 + hs * 16);
        cp16(sb + OFF_AL + hr * 80 + hs * 16,
             Al + (size_t)hr * pitchA2 + kc2 + hs * 16);
        cp16(sb + OFF_BF + bk * 272 + bs * 16,
             Bf + (size_t)(c * KC + bk) * pitchBf + bs * 16);
        cp16(sb + (tsel ? OFF_BL : OFF_BH) + tr * 80 + ts * 16,
             (tsel ? Bl : Bh) + (size_t)tr * pitchB2 + kc2 + ts * 16);
        asm volatile("cp.async.commit_group;");
    };

#pragma unroll
    for (int s = 0; s < NSTAGE - 1; ++s) load_stage(s, s);

    // fma-path constants
    const int ft   = tid;                  // valid when wid < 8
    const int colg = ft & 15;
    const int rowg = ft >> 4;
    // tensor-path constants
    const int wid2 = wid - 8;
    const int wm = (wid2 & 3) * 32;
    const int wn = (wid2 >> 2) * 32;
    const uint32_t aoff = (uint32_t)((wm + (lane & 15)) * 80 + ((lane >> 4) & 1) * 16);
    const uint32_t boff = (uint32_t)((wn + (lane & 7)) * 80 + ((lane >> 3) & 1) * 16);

#pragma unroll 1
    for (int c = 0; c < chunks; ++c) {
        asm volatile("cp.async.wait_group %0;" :: "n"(NSTAGE - 2) : "memory");
        __syncthreads();

        if (c + NSTAGE - 1 < chunks)
            load_stage((c + NSTAGE - 1) & (NSTAGE - 1), c + NSTAGE - 1);

        const uint32_t sb = sbase + (c & (NSTAGE - 1)) * STAGE_B;

        if (wid < 8) {
            // fp32 FFMA2 path: 8 rows x 4 cols, k-pair lanes
            const uint32_t aAdr = sb + OFF_AF + rowg * 8 * 144;
            const uint32_t bAdr = sb + OFF_BF + colg * 16;
#pragma unroll
            for (int kp = 0; kp < 16; ++kp) {
                ull a[8];
#pragma unroll
                for (int i = 0; i < 8; ++i)
                    asm volatile("ld.shared.b64 %0, [%1];" : "=l"(a[i])
                                 : "r"(aAdr + i * 144 + kp * 8));
                float4 b0, b1;
                asm volatile("ld.shared.v4.f32 {%0,%1,%2,%3}, [%4];"
                             : "=f"(b0.x), "=f"(b0.y), "=f"(b0.z), "=f"(b0.w)
                             : "r"(bAdr + (2 * kp) * 272));
                asm volatile("ld.shared.v4.f32 {%0,%1,%2,%3}, [%4];"
                             : "=f"(b1.x), "=f"(b1.y), "=f"(b1.z), "=f"(b1.w)
                             : "r"(bAdr + (2 * kp + 1) * 272));
                ull bp[4];
                bp[0] = pack2(b0.x, b1.x); bp[1] = pack2(b0.y, b1.y);
                bp[2] = pack2(b0.z, b1.z); bp[3] = pack2(b0.w, b1.w);
#pragma unroll
                for (int i = 0; i < 8; ++i)
#pragma unroll
                    for (int j = 0; j < 4; ++j)
                        accf[i][j] = f2_fma(a[i], bp[j], accf[i][j]);
            }
        } else {
            // bf16 3-term HMMA path: warp tile 32x32 on cols [64,128)
#pragma unroll
            for (int ks = 0; ks < 2; ++ks) {
                const int kb = ks * 32;
                uint32_t ah[2][4], al[2][4], bh[4][2], bl[4][2];
#pragma unroll
                for (int mi = 0; mi < 2; ++mi) {
                    const uint32_t ad = aoff + kb + mi * 16 * 80;
                    ldsm4(ah[mi], sb + OFF_AH + ad);
                    ldsm4(al[mi], sb + OFF_AL + ad);
                }
#pragma unroll
                for (int ni = 0; ni < 4; ++ni) {
                    const uint32_t bd = boff + kb + ni * 8 * 80;
                    ldsm2(bh[ni], sb + OFF_BH + bd);
                    ldsm2(bl[ni], sb + OFF_BL + bd);
                }
#pragma unroll
                for (int mi = 0; mi < 2; ++mi)
#pragma unroll
                    for (int ni = 0; ni < 4; ++ni)
                        mmabf16(acct[mi][ni], ah[mi], bh[ni]);
#pragma unroll
                for (int mi = 0; mi < 2; ++mi)
#pragma unroll
                    for (int ni = 0; ni < 4; ++ni)
                        mmabf16(acct[mi][ni], al[mi], bh[ni]);
#pragma unroll
                for (int mi = 0; mi < 2; ++mi)
#pragma unroll
                    for (int ni = 0; ni < 4; ++ni)
                        mmabf16(acct[mi][ni], ah[mi], bl[ni]);
            }
        }
    }
}

#define ACC_INIT \
    ull accf[8][4]; float acct[2][4][4]; \
    _Pragma("unroll") for (int i = 0; i < 8; ++i) \
    _Pragma("unroll") for (int j = 0; j < 4; ++j) accf[i][j] = 0ULL; \
    _Pragma("unroll") for (int mi = 0; mi < 2; ++mi) \
    _Pragma("unroll") for (int ni = 0; ni < 4; ++ni) \
    _Pragma("unroll") for (int k = 0; k < 4; ++k) acct[mi][ni][k] = 0.f;

// ---------------- GEMM1: h = relu(disp @ w1 + b1) -> hf, h_hi/lo ----------------
__global__ __launch_bounds__(NTHREADS, 1) void gemm1_hyb(
    const float* __restrict__ w1, const float* __restrict__ b1)
{
    extern __shared__ char smem[];
    const int tid = threadIdx.x;
    const int wid = tid >> 5, lane = tid & 31;
    const int row0 = blockIdx.y * 128;
    const int col0 = blockIdx.x * 128;
    const int e    = row0 >> 10;

    ACC_INIT;
    hybrid_mainloop(
        (const char*)(g_dispf + (size_t)row0 * M_DIM),
        (const char*)(g_disp_hi + (size_t)row0 * M_DIM),
        (const char*)(g_disp_lo + (size_t)row0 * M_DIM),
        (const char*)(w1 + (size_t)e * M_DIM * H_DIM + col0),
        (size_t)H_DIM * 4,
        (const char*)(g_w1t_hi + ((size_t)e * H_DIM + col0 + 64) * M_DIM),
        (const char*)(g_w1t_lo + ((size_t)e * H_DIM + col0 + 64) * M_DIM),
        (size_t)M_DIM * 2,
        (size_t)M_DIM * 4, (size_t)M_DIM * 2, M_DIM / KC, smem,
        accf, acct);

    const float* b1g = b1 + (size_t)e * H_DIM;

    if (wid < 8) {
        const int colg = tid & 15, rowg = tid >> 4;
        const int cg = col0 + colg * 4;
#pragma unroll
        for (int i = 0; i < 8; ++i) {
            const int r = row0 + rowg * 8 + i;
            float v[4];
#pragma unroll
            for (int j = 0; j < 4; ++j) {
                float2 u = unpack2(accf[i][j]);
                v[j] = fmaxf(u.x + u.y + b1g[cg + j], 0.f);
            }
            *(float4*)(g_hf + (size_t)r * H_DIM + cg) =
                make_float4(v[0], v[1], v[2], v[3]);
            __nv_bfloat16 hh[4], ll[4];
#pragma unroll
            for (int j = 0; j < 4; ++j) bsplit(v[j], hh[j], ll[j]);
            *(uint2*)(g_h_hi + (size_t)r * H_DIM + cg) = *(uint2*)hh;
            *(uint2*)(g_h_lo + (size_t)r * H_DIM + cg) = *(uint2*)ll;
        }
    } else {
        const int wid2 = wid - 8;
        const int wm = (wid2 & 3) * 32;
        const int wn = (wid2 >> 2) * 32;
#pragma unroll
        for (int ni = 0; ni < 4; ++ni) {
            const int cg = col0 + 64 + wn + ni * 8 + (lane & 3) * 2;
            const float bv0 = b1g[cg], bv1 = b1g[cg + 1];
#pragma unroll
            for (int mi = 0; mi < 2; ++mi)
#pragma unroll
                for (int h = 0; h < 2; ++h) {
                    const int r = row0 + wm + mi * 16 + (lane >> 2) + h * 8;
                    float v0 = fmaxf(acct[mi][ni][h * 2 + 0] + bv0, 0.f);
                    float v1 = fmaxf(acct[mi][ni][h * 2 + 1] + bv1, 0.f);
                    *(float2*)(g_hf + (size_t)r * H_DIM + cg) = make_float2(v0, v1);
                    __nv_bfloat16 h0, l0, h1, l1;
                    bsplit(v0, h0, l0); bsplit(v1, h1, l1);
                    *(__nv_bfloat162*)(g_h_hi + (size_t)r * H_DIM + cg) =
                        __nv_bfloat162(h0, h1);
                    *(__nv_bfloat162*)(g_h_lo + (size_t)r * H_DIM + cg) =
                        __nv_bfloat162(l0, l1);
                }
        }
    }
}

// ---------------- GEMM2: out = gate1 * (h @ w2 + b2), scatter ----------------
__global__ __launch_bounds__(NTHREADS, 1) void gemm2_hyb(
    const float* __restrict__ w2, const float* __restrict__ b2,
    float* __restrict__ out)
{
    extern __shared__ char smem[];
    const int tid = threadIdx.x;
    const int wid = tid >> 5, lane = tid & 31;
    const int row0 = blockIdx.y * 128;
    const int col0 = blockIdx.x * 128;
    const int e    = row0 >> 10;

    ACC_INIT;
    hybrid_mainloop(
        (const char*)(g_hf + (size_t)row0 * H_DIM),
        (const char*)(g_h_hi + (size_t)row0 * H_DIM),
        (const char*)(g_h_lo + (size_t)row0 * H_DIM),
        (const char*)(w2 + (size_t)e * H_DIM * M_DIM + col0),
        (size_t)M_DIM * 4,
        (const char*)(g_w2t_hi + ((size_t)e * M_DIM + col0 + 64) * H_DIM),
        (const char*)(g_w2t_lo + ((size_t)e * M_DIM + col0 + 64) * H_DIM),
        (size_t)H_DIM * 2,
        (size_t)H_DIM * 4, (size_t)H_DIM * 2, H_DIM / KC, smem,
        accf, acct);

    const float* b2g = b2 + (size_t)e * M_DIM;

    if (wid < 8) {
        const int colg = tid & 15, rowg = tid >> 4;
        const int cg = col0 + colg * 4;
#pragma unroll
        for (int i = 0; i < 8; ++i) {
            const int r = row0 + rowg * 8 + i;
            const int t = g_s2t[r];
            if (t < 0) continue;
            const float g = g_gate1[t];
            float v[4];
#pragma unroll
            for (int j = 0; j < 4; ++j) {
                float2 u = unpack2(accf[i][j]);
                v[j] = (u.x + u.y + b2g[cg + j]) * g;
            }
            *(float4*)(out + (size_t)t * M_DIM + cg) =
                make_float4(v[0], v[1], v[2], v[3]);
        }
    } else {
        const int wid2 = wid - 8;
        const int wm = (wid2 & 3) * 32;
        const int wn = (wid2 >> 2) * 32;
#pragma unroll
        for (int ni = 0; ni < 4; ++ni) {
            const int cg = col0 + 64 + wn + ni * 8 + (lane & 3) * 2;
            const float bv0 = b2g[cg], bv1 = b2g[cg + 1];
#pragma unroll
            for (int mi = 0; mi < 2; ++mi)
#pragma unroll
                for (int h = 0; h < 2; ++h) {
                    const int r = row0 + wm + mi * 16 + (lane >> 2) + h * 8;
                    const int t = g_s2t[r];
                    if (t < 0) continue;
                    const float g = g_gate1[t];
                    float2 v;
                    v.x = (acct[mi][ni][h * 2 + 0] + bv0) * g;
                    v.y = (acct[mi][ni][h * 2 + 1] + bv1) * g;
                    *(float2*)(out + (size_t)t * M_DIM + cg) = v;
                }
        }
    }
}

// ---------------- launch ----------------
extern "C" void kernel_launch(void* const* d_in, const int* in_sizes, int n_in,
                              void* d_out, int out_size)
{
    const float* x  = (const float*)d_in[0];
    const float* wg = (const float*)d_in[1];
    const float* w1 = (const float*)d_in[2];
    const float* b1 = (const float*)d_in[3];
    const float* w2 = (const float*)d_in[4];
    const float* b2 = (const float*)d_in[5];
    float* out = (float*)d_out;

    cudaFuncSetAttribute(gemm1_hyb, cudaFuncAttributeMaxDynamicSharedMemorySize,
                         SMEM_BYTES);
    cudaFuncSetAttribute(gemm2_hyb, cudaFuncAttributeMaxDynamicSharedMemorySize,
                         SMEM_BYTES);

    __nv_bfloat16 *w1t_hi, *w1t_lo, *w2t_hi, *w2t_lo;
    cudaGetSymbolAddress((void**)&w1t_hi, g_w1t_hi);
    cudaGetSymbolAddress((void**)&w1t_lo, g_w1t_lo);
    cudaGetSymbolAddress((void**)&w2t_hi, g_w2t_hi);
    cudaGetSymbolAddress((void**)&w2t_lo, g_w2t_lo);

    init_kernel<<<256, 256>>>(out);

    // bf16 planes only for tensor-half columns
    wsplit_kernel<<<dim3(H_DIM / 64, M_DIM / 32, E_NUM), dim3(32, 8)>>>(
        w1, w1t_hi, w1t_lo, M_DIM, H_DIM);
    wsplit_kernel<<<dim3(M_DIM / 64, H_DIM / 32, E_NUM), dim3(32, 8)>>>(
        w2, w2t_hi, w2t_lo, H_DIM, M_DIM);

    gate_kernel<<<N_TOK, 256>>>(x, wg);
    sched_kernel<<<1, 256>>>(out, (out_size > N_TOK * M_DIM) ? 1 : 0);
    disp_kernel<<<EC_SLOTS, 256>>>(x);

    gemm1_hyb<<<dim3(H_DIM / 128, EC_SLOTS / 128), NTHREADS, SMEM_BYTES>>>(w1, b1);
    gemm2_hyb<<<dim3(M_DIM / 128, EC_SLOTS / 128), NTHREADS, SMEM_BYTES>>>(w2, b2, out);
}

// round 12
// speedup vs baseline: 2.0229x; 1.7189x over previous
#include <cuda_runtime.h>
#include <cuda_bf16.h>
#include <cstdint>

typedef unsigned long long ull;

#define N_TOK    8192
#define M_DIM    2048
#define E_NUM    8
#define H_DIM    8192
#define C_CAP    1024
#define EC_SLOTS 8192

#define KC       32
// stage layout (bytes)
#define OFF_AF   0                        // fp32 A: 128 rows x 144B
#define OFF_BF   18432                    // fp32 B: 32 k-rows x 144B
#define OFF_AH   23040                    // bf16 A hi: 128 x 80B
#define OFF_AL   33280
#define OFF_BH   43520                    // bf16 B hi: 96 x 80B
#define OFF_BL   51200
#define STAGE_B  58880
#define NSTAGE   3
#define SMEM_BYTES (NSTAGE * STAGE_B)     // 176640
#define NTHREADS 512
#define FMA_COLS 32

__device__ int    g_idx  [N_TOK];
__device__ float  g_gate1[N_TOK];
__device__ float  g_gates[N_TOK * E_NUM];
__device__ int    g_s2t  [EC_SLOTS];

__device__ float         g_dispf  [(size_t)EC_SLOTS * M_DIM];
__device__ __nv_bfloat16 g_disp_hi[(size_t)EC_SLOTS * M_DIM];
__device__ __nv_bfloat16 g_disp_lo[(size_t)EC_SLOTS * M_DIM];
__device__ float         g_hf     [(size_t)EC_SLOTS * H_DIM];
__device__ __nv_bfloat16 g_h_hi   [(size_t)EC_SLOTS * H_DIM];
__device__ __nv_bfloat16 g_h_lo   [(size_t)EC_SLOTS * H_DIM];
__device__ __nv_bfloat16 g_w1t_hi[(size_t)E_NUM * H_DIM * M_DIM];
__device__ __nv_bfloat16 g_w1t_lo[(size_t)E_NUM * H_DIM * M_DIM];
__device__ __nv_bfloat16 g_w2t_hi[(size_t)E_NUM * M_DIM * H_DIM];
__device__ __nv_bfloat16 g_w2t_lo[(size_t)E_NUM * M_DIM * H_DIM];

__device__ __forceinline__ uint32_t s2u(const void* p) {
    return (uint32_t)__cvta_generic_to_shared(p);
}
__device__ __forceinline__ void cp16(uint32_t s, const void* g) {
    asm volatile("cp.async.cg.shared.global [%0], [%1], 16;" :: "r"(s), "l"(g));
}
__device__ __forceinline__ void ldsm4(uint32_t* r, uint32_t a) {
    asm volatile("ldmatrix.sync.aligned.m8n8.x4.shared.b16 {%0,%1,%2,%3}, [%4];"
                 : "=r"(r[0]), "=r"(r[1]), "=r"(r[2]), "=r"(r[3]) : "r"(a));
}
__device__ __forceinline__ void ldsm2(uint32_t* r, uint32_t a) {
    asm volatile("ldmatrix.sync.aligned.m8n8.x2.shared.b16 {%0,%1}, [%2];"
                 : "=r"(r[0]), "=r"(r[1]) : "r"(a));
}
__device__ __forceinline__ void mmabf16(float* d, const uint32_t* a, const uint32_t* b) {
    asm volatile("mma.sync.aligned.m16n8k16.row.col.f32.bf16.bf16.f32 "
                 "{%0,%1,%2,%3}, {%4,%5,%6,%7}, {%8,%9}, {%0,%1,%2,%3};"
                 : "+f"(d[0]), "+f"(d[1]), "+f"(d[2]), "+f"(d[3])
                 : "r"(a[0]), "r"(a[1]), "r"(a[2]), "r"(a[3]),
                   "r"(b[0]), "r"(b[1]));
}
__device__ __forceinline__ ull f2_fma(ull a, ull b, ull c) {
    ull d;
    asm("fma.rn.f32x2 %0, %1, %2, %3;" : "=l"(d) : "l"(a), "l"(b), "l"(c));
    return d;
}
__device__ __forceinline__ ull pack2(float lo, float hi) {
    ull d;
    asm("mov.b64 %0, {%1, %2};" : "=l"(d) : "f"(lo), "f"(hi));
    return d;
}
__device__ __forceinline__ float2 unpack2(ull v) {
    float2 r;
    asm("mov.b64 {%0, %1}, %2;" : "=f"(r.x), "=f"(r.y) : "l"(v));
    return r;
}
__device__ __forceinline__ float lds32(uint32_t a) {
    float v;
    asm volatile("ld.shared.f32 %0, [%1];" : "=f"(v) : "r"(a));
    return v;
}
__device__ __forceinline__ float4 lds128(uint32_t a) {
    float4 v;
    asm volatile("ld.shared.v4.f32 {%0,%1,%2,%3}, [%4];"
                 : "=f"(v.x), "=f"(v.y), "=f"(v.z), "=f"(v.w) : "r"(a));
    return v;
}
__device__ __forceinline__ void bsplit(float f, __nv_bfloat16& hi, __nv_bfloat16& lo) {
    hi = __float2bfloat16(f);
    lo = __float2bfloat16(f - __bfloat162float(hi));
}

// ---------------- init ----------------
__global__ void init_kernel(float* __restrict__ out)
{
    int tid = blockIdx.x * blockDim.x + threadIdx.x;
    if (tid < EC_SLOTS) g_s2t[tid] = -1;
    float4* o4 = (float4*)out;
    const int n4 = (N_TOK * M_DIM) / 4;
    const int stride = gridDim.x * blockDim.x;
    for (int i = tid; i < n4; i += stride)
        o4[i] = make_float4(0.f, 0.f, 0.f, 0.f);
}

// ---------------- gate ----------------
__global__ __launch_bounds__(256) void gate_kernel(
    const float* __restrict__ x, const float* __restrict__ wg)
{
    __shared__ float sx[M_DIM];
    __shared__ float slog[E_NUM];
    const int tok = blockIdx.x, tid = threadIdx.x;

    const float4* xr = (const float4*)(x + (size_t)tok * M_DIM);
    float4* sx4 = (float4*)sx;
    for (int i = tid; i < M_DIM / 4; i += 256) sx4[i] = xr[i];
    __syncthreads();

    const int wid = tid >> 5, lane = tid & 31;
    const float* __restrict__ w = wg + wid * M_DIM;
    float sum = 0.f;
    for (int m = lane; m < M_DIM; m += 32) sum = fmaf(sx[m], w[m], sum);
#pragma unroll
    for (int o = 16; o; o >>= 1) sum += __shfl_xor_sync(0xffffffffu, sum, o);
    if (lane == 0) slog[wid] = sum;
    __syncthreads();

    if (tid == 0) {
        float mx = slog[0]; int am = 0;
#pragma unroll
        for (int e = 1; e < E_NUM; ++e)
            if (slog[e] > mx) { mx = slog[e]; am = e; }
        float ge[E_NUM], den = 0.f;
#pragma unroll
        for (int e = 0; e < E_NUM; ++e) { ge[e] = expf(slog[e] - mx); den += ge[e]; }
        const float inv = 1.f / den;
#pragma unroll
        for (int e = 0; e < E_NUM; ++e) g_gates[tok * E_NUM + e] = ge[e] * inv;
        g_idx[tok]   = am;
        g_gate1[tok] = ge[am] * inv;
    }
}

// ---------------- sched ----------------
__global__ __launch_bounds__(256) void sched_kernel(float* __restrict__ out,
                                                    int write_laux)
{
    __shared__ int   s_ce[E_NUM];
    __shared__ float s_me[E_NUM];
    const int tid = threadIdx.x;
    const int wid = tid >> 5, lane = tid & 31;

    int count = 0;
    for (int base = 0; base < N_TOK; base += 32) {
        const int tok = base + lane;
        const bool mine = (g_idx[tok] == wid);
        const unsigned bal = __ballot_sync(0xffffffffu, mine);
        if (mine) {
            const int loc = count + __popc(bal & ((1u << lane) - 1u));
            if (loc < C_CAP) g_s2t[wid * C_CAP + loc] = tok;
        }
        count += __popc(bal);
    }
    if (lane == 0) s_ce[wid] = count;

    float me = 0.f;
    for (int t = lane; t < N_TOK; t += 32) me += g_gates[t * E_NUM + wid];
#pragma unroll
    for (int o = 16; o; o >>= 1) me += __shfl_xor_sync(0xffffffffu, me, o);
    if (lane == 0) s_me[wid] = me;
    __syncthreads();

    if (tid == 0 && write_laux) {
        float acc = 0.f;
#pragma unroll
        for (int e = 0; e < E_NUM; ++e) acc += s_me[e] * (float)s_ce[e];
        out[(size_t)N_TOK * M_DIM] =
            acc * ((float)E_NUM / ((float)N_TOK * (float)N_TOK));
    }
}

// ---------------- disp: gather rows -> fp32 + bf16 hi/lo ----------------
__global__ __launch_bounds__(256) void disp_kernel(const float* __restrict__ x)
{
    const int slot = blockIdx.x;
    const int t = g_s2t[slot];
    const float4* src = (t >= 0) ? (const float4*)(x + (size_t)t * M_DIM) : nullptr;
    float4*        df = (float4*)(g_dispf + (size_t)slot * M_DIM);
    __nv_bfloat16* dh = g_disp_hi + (size_t)slot * M_DIM;
    __nv_bfloat16* dl = g_disp_lo + (size_t)slot * M_DIM;
    for (int i = threadIdx.x; i < M_DIM / 4; i += 256) {
        float4 v = src ? src[i] : make_float4(0.f, 0.f, 0.f, 0.f);
        df[i] = v;
        __nv_bfloat16 hh[4], ll[4];
        bsplit(v.x, hh[0], ll[0]); bsplit(v.y, hh[1], ll[1]);
        bsplit(v.z, hh[2], ll[2]); bsplit(v.w, hh[3], ll[3]);
        *(uint2*)(dh + i * 4) = *(uint2*)hh;
        *(uint2*)(dl + i * 4) = *(uint2*)ll;
    }
}

// ---------------- wsplit: bf16 planes for tensor columns only ----------------
// col groups with (c0 mod 128) in {32, 64, 96}
__global__ void wsplit_kernel(const float* __restrict__ src,
                              __nv_bfloat16* __restrict__ dhi,
                              __nv_bfloat16* __restrict__ dlo,
                              int R, int C)
{
    __shared__ float tile[32][33];
    const int e  = blockIdx.z;
    const int bx = blockIdx.x;
    const int c0 = (bx / 3) * 128 + 32 + (bx % 3) * 32;
    const int r0 = blockIdx.y * 32;
    const int tx = threadIdx.x, ty = threadIdx.y;

    const float* s = src + (size_t)e * R * C;
#pragma unroll
    for (int i = 0; i < 4; ++i)
        tile[ty + 8 * i][tx] = s[(size_t)(r0 + ty + 8 * i) * C + c0 + tx];
    __syncthreads();

    __nv_bfloat16* dh = dhi + (size_t)e * C * R;
    __nv_bfloat16* dl = dlo + (size_t)e * C * R;
#pragma unroll
    for (int i = 0; i < 4; ++i) {
        const int c = c0 + ty + 8 * i;
        const int r = r0 + tx;
        __nv_bfloat16 hi, lo;
        bsplit(tile[tx][ty + 8 * i], hi, lo);
        dh[(size_t)c * R + r] = hi;
        dl[(size_t)c * R + r] = lo;
    }
}

// ---------------- loader mapping: 3072 16B units, 6 per thread ----------------
struct LoadMap { uint32_t so[6]; const char* gb[6]; int ks[6]; };

__device__ __forceinline__ void make_map(
    LoadMap& m, int tid,
    const char* Af, size_t pitchAf,
    const char* Bf, size_t pitchBf,
    const char* Ah, const char* Al, size_t pitchA2,
    const char* Bh, const char* Bl, size_t pitchB2)
{
#pragma unroll
    for (int i = 0; i < 6; ++i) {
        const int g = i * 512 + tid;
        if (g < 1024) {                       // Af: 128 rows x 8 segs
            const int row = g >> 3, seg = g & 7;
            m.so[i] = OFF_AF + row * 144 + seg * 16;
            m.gb[i] = Af + (size_t)row * pitchAf + seg * 16;
            m.ks[i] = KC * 4;
        } else if (g < 1280) {                // Bf: 32 k-rows x 8 segs
            const int u = g - 1024, row = u >> 3, seg = u & 7;
            m.so[i] = OFF_BF + row * 144 + seg * 16;
            m.gb[i] = Bf + (size_t)row * pitchBf + seg * 16;
            m.ks[i] = (int)(KC * pitchBf);
        } else if (g < 1792) {                // Ah: 128 rows x 4 segs
            const int u = g - 1280, row = u >> 2, seg = u & 3;
            m.so[i] = OFF_AH + row * 80 + seg * 16;
            m.gb[i] = Ah + (size_t)row * pitchA2 + seg * 16;
            m.ks[i] = KC * 2;
        } else if (g < 2304) {                // Al
            const int u = g - 1792, row = u >> 2, seg = u & 3;
            m.so[i] = OFF_AL + row * 80 + seg * 16;
            m.gb[i] = Al + (size_t)row * pitchA2 + seg * 16;
            m.ks[i] = KC * 2;
        } else if (g < 2688) {                // Bh: 96 rows x 4 segs
            const int u = g - 2304, row = u >> 2, seg = u & 3;
            m.so[i] = OFF_BH + row * 80 + seg * 16;
            m.gb[i] = Bh + (size_t)row * pitchB2 + seg * 16;
            m.ks[i] = KC * 2;
        } else {                              // Bl
            const int u = g - 2688, row = u >> 2, seg = u & 3;
            m.so[i] = OFF_BL + row * 80 + seg * 16;
            m.gb[i] = Bl + (size_t)row * pitchB2 + seg * 16;
            m.ks[i] = KC * 2;
        }
    }
}

__device__ __forceinline__ void load_stage(uint32_t sbase, int st, int c,
                                           const LoadMap& m)
{
    const uint32_t sb = sbase + st * STAGE_B;
#pragma unroll
    for (int i = 0; i < 6; ++i)
        cp16(sb + m.so[i], m.gb[i] + (size_t)c * (size_t)m.ks[i]);
    asm volatile("cp.async.commit_group;");
}

// ---------------- fma path: cols [0,32), 4 warps, FFMA2 row-pair lanes ------
__device__ __forceinline__ void fma_loop(uint32_t sbase, int chunks,
                                         const LoadMap& m, ull accf[4][4],
                                         int wid, int lane)
{
    const int r4 = lane & 3, colg = lane >> 2;
    const uint32_t aBase = OFF_AF + (uint32_t)(wid * 32 + r4 * 2) * 144;
    const uint32_t bBase = OFF_BF + (uint32_t)colg * 16;

#pragma unroll 1
    for (int c = 0; c < chunks; ++c) {
        asm volatile("cp.async.wait_group %0;" :: "n"(NSTAGE - 2) : "memory");
        __syncthreads();
        if (c + NSTAGE - 1 < chunks)
            load_stage(sbase, (c + NSTAGE - 1) % NSTAGE, c + NSTAGE - 1, m);
        const uint32_t sb = sbase + (c % NSTAGE) * STAGE_B;
#pragma unroll 4
        for (int k = 0; k < KC; ++k) {
            float4 bv = lds128(sb + bBase + k * 144);
            ull bp[4];
            bp[0] = pack2(bv.x, bv.x); bp[1] = pack2(bv.y, bv.y);
            bp[2] = pack2(bv.z, bv.z); bp[3] = pack2(bv.w, bv.w);
#pragma unroll
            for (int p = 0; p < 4; ++p) {
                const uint32_t ra = sb + aBase + p * (8 * 144) + k * 4;
                ull ap = pack2(lds32(ra), lds32(ra + 144));
#pragma unroll
                for (int j = 0; j < 4; ++j)
                    accf[p][j] = f2_fma(ap, bp[j], accf[p][j]);
            }
        }
    }
}

// ---------------- tensor path: cols [32,128), 12 warps, 3-term bf16 --------
__device__ __forceinline__ void mma_loop(uint32_t sbase, int chunks,
                                         const LoadMap& m, float acct[2][4][4],
                                         int wid2, int lane)
{
    const int wm  = (wid2 & 3) * 32;
    const int wnl = (wid2 >> 2) * 32;
    const uint32_t aoff = (uint32_t)((wm + (lane & 15)) * 80 + ((lane >> 4) & 1) * 16);
    const uint32_t boff = (uint32_t)((wnl + (lane & 7)) * 80 + ((lane >> 3) & 1) * 16);

#pragma unroll 1
    for (int c = 0; c < chunks; ++c) {
        asm volatile("cp.async.wait_group %0;" :: "n"(NSTAGE - 2) : "memory");
        __syncthreads();
        if (c + NSTAGE - 1 < chunks)
            load_stage(sbase, (c + NSTAGE - 1) % NSTAGE, c + NSTAGE - 1, m);
        const uint32_t sb = sbase + (c % NSTAGE) * STAGE_B;
#pragma unroll
        for (int ks = 0; ks < 2; ++ks) {
            const int kb = ks * 32;
            uint32_t ah[2][4], al[2][4], bh[4][2], bl[4][2];
#pragma unroll
            for (int mi = 0; mi < 2; ++mi) {
                const uint32_t ad = aoff + kb + mi * 16 * 80;
                ldsm4(ah[mi], sb + OFF_AH + ad);
                ldsm4(al[mi], sb + OFF_AL + ad);
            }
#pragma unroll
            for (int ni = 0; ni < 4; ++ni) {
                const uint32_t bd = boff + kb + ni * 8 * 80;
                ldsm2(bh[ni], sb + OFF_BH + bd);
                ldsm2(bl[ni], sb + OFF_BL + bd);
            }
#pragma unroll
            for (int mi = 0; mi < 2; ++mi)
#pragma unroll
                for (int ni = 0; ni < 4; ++ni)
                    mmabf16(acct[mi][ni], ah[mi], bh[ni]);
#pragma unroll
            for (int mi = 0; mi < 2; ++mi)
#pragma unroll
                for (int ni = 0; ni < 4; ++ni)
                    mmabf16(acct[mi][ni], al[mi], bh[ni]);
#pragma unroll
            for (int mi = 0; mi < 2; ++mi)
#pragma unroll
                for (int ni = 0; ni < 4; ++ni)
                    mmabf16(acct[mi][ni], ah[mi], bl[ni]);
        }
    }
}

// ---------------- GEMM1 ----------------
__global__ __launch_bounds__(NTHREADS, 1) void gemm1_hyb(
    const float* __restrict__ w1, const float* __restrict__ b1)
{
    extern __shared__ char smem[];
    const uint32_t sbase = s2u(smem);
    const int tid = threadIdx.x;
    const int wid = tid >> 5, lane = tid & 31;
    const int row0 = blockIdx.y * 128;
    const int col0 = blockIdx.x * 128;
    const int e    = row0 >> 10;
    const int chunks = M_DIM / KC;

    LoadMap m;
    make_map(m, tid,
        (const char*)(g_dispf + (size_t)row0 * M_DIM), (size_t)M_DIM * 4,
        (const char*)(w1 + (size_t)e * M_DIM * H_DIM + col0), (size_t)H_DIM * 4,
        (const char*)(g_disp_hi + (size_t)row0 * M_DIM),
        (const char*)(g_disp_lo + (size_t)row0 * M_DIM), (size_t)M_DIM * 2,
        (const char*)(g_w1t_hi + ((size_t)e * H_DIM + col0 + FMA_COLS) * M_DIM),
        (const char*)(g_w1t_lo + ((size_t)e * H_DIM + col0 + FMA_COLS) * M_DIM),
        (size_t)M_DIM * 2);

#pragma unroll
    for (int s = 0; s < NSTAGE - 1; ++s) load_stage(sbase, s, s, m);

    const float* b1g = b1 + (size_t)e * H_DIM;

    if (wid < 4) {
        ull accf[4][4];
#pragma unroll
        for (int p = 0; p < 4; ++p)
#pragma unroll
            for (int j = 0; j < 4; ++j) accf[p][j] = 0ULL;
        fma_loop(sbase, chunks, m, accf, wid, lane);

        const int r4 = lane & 3, colg = lane >> 2;
        const int cg = col0 + colg * 4;
        float bb[4];
#pragma unroll
        for (int j = 0; j < 4; ++j) bb[j] = b1g[cg + j];
#pragma unroll
        for (int p = 0; p < 4; ++p) {
            const int r = row0 + wid * 32 + r4 * 2 + p * 8;
            float ve[4], vo[4];
#pragma unroll
            for (int j = 0; j < 4; ++j) {
                float2 u = unpack2(accf[p][j]);
                ve[j] = fmaxf(u.x + bb[j], 0.f);
                vo[j] = fmaxf(u.y + bb[j], 0.f);
            }
            *(float4*)(g_hf + (size_t)r * H_DIM + cg) =
                make_float4(ve[0], ve[1], ve[2], ve[3]);
            *(float4*)(g_hf + (size_t)(r + 1) * H_DIM + cg) =
                make_float4(vo[0], vo[1], vo[2], vo[3]);
            __nv_bfloat16 hh[4], ll[4];
#pragma unroll
            for (int j = 0; j < 4; ++j) bsplit(ve[j], hh[j], ll[j]);
            *(uint2*)(g_h_hi + (size_t)r * H_DIM + cg) = *(uint2*)hh;
            *(uint2*)(g_h_lo + (size_t)r * H_DIM + cg) = *(uint2*)ll;
#pragma unroll
            for (int j = 0; j < 4; ++j) bsplit(vo[j], hh[j], ll[j]);
            *(uint2*)(g_h_hi + (size_t)(r + 1) * H_DIM + cg) = *(uint2*)hh;
            *(uint2*)(g_h_lo + (size_t)(r + 1) * H_DIM + cg) = *(uint2*)ll;
        }
    } else {
        float acct[2][4][4];
#pragma unroll
        for (int mi = 0; mi < 2; ++mi)
#pragma unroll
            for (int ni = 0; ni < 4; ++ni)
#pragma unroll
                for (int k = 0; k < 4; ++k) acct[mi][ni][k] = 0.f;
        const int wid2 = wid - 4;
        mma_loop(sbase, chunks, m, acct, wid2, lane);

        const int wm  = (wid2 & 3) * 32;
        const int wnl = (wid2 >> 2) * 32;
#pragma unroll
        for (int ni = 0; ni < 4; ++ni) {
            const int cg = col0 + FMA_COLS + wnl + ni * 8 + (lane & 3) * 2;
            const float bv0 = b1g[cg], bv1 = b1g[cg + 1];
#pragma unroll
            for (int mi = 0; mi < 2; ++mi)
#pragma unroll
                for (int h = 0; h < 2; ++h) {
                    const int r = row0 + wm + mi * 16 + (lane >> 2) + h * 8;
                    float v0 = fmaxf(acct[mi][ni][h * 2 + 0] + bv0, 0.f);
                    float v1 = fmaxf(acct[mi][ni][h * 2 + 1] + bv1, 0.f);
                    *(float2*)(g_hf + (size_t)r * H_DIM + cg) = make_float2(v0, v1);
                    __nv_bfloat16 h0, l0, h1, l1;
                    bsplit(v0, h0, l0); bsplit(v1, h1, l1);
                    *(__nv_bfloat162*)(g_h_hi + (size_t)r * H_DIM + cg) =
                        __nv_bfloat162(h0, h1);
                    *(__nv_bfloat162*)(g_h_lo + (size_t)r * H_DIM + cg) =
                        __nv_bfloat162(l0, l1);
                }
        }
    }
}

// ---------------- GEMM2 ----------------
__global__ __launch_bounds__(NTHREADS, 1) void gemm2_hyb(
    const float* __restrict__ w2, const float* __restrict__ b2,
    float* __restrict__ out)
{
    extern __shared__ char smem[];
    const uint32_t sbase = s2u(smem);
    const int tid = threadIdx.x;
    const int wid = tid >> 5, lane = tid & 31;
    const int row0 = blockIdx.y * 128;
    const int col0 = blockIdx.x * 128;
    const int e    = row0 >> 10;
    const int chunks = H_DIM / KC;

    LoadMap m;
    make_map(m, tid,
        (const char*)(g_hf + (size_t)row0 * H_DIM), (size_t)H_DIM * 4,
        (const char*)(w2 + (size_t)e * H_DIM * M_DIM + col0), (size_t)M_DIM * 4,
        (const char*)(g_h_hi + (size_t)row0 * H_DIM),
        (const char*)(g_h_lo + (size_t)row0 * H_DIM), (size_t)H_DIM * 2,
        (const char*)(g_w2t_hi + ((size_t)e * M_DIM + col0 + FMA_COLS) * H_DIM),
        (const char*)(g_w2t_lo + ((size_t)e * M_DIM + col0 + FMA_COLS) * H_DIM),
        (size_t)H_DIM * 2);

#pragma unroll
    for (int s = 0; s < NSTAGE - 1; ++s) load_stage(sbase, s, s, m);

    const float* b2g = b2 + (size_t)e * M_DIM;

    if (wid < 4) {
        ull accf[4][4];
#pragma unroll
        for (int p = 0; p < 4; ++p)
#pragma unroll
            for (int j = 0; j < 4; ++j) accf[p][j] = 0ULL;
        fma_loop(sbase, chunks, m, accf, wid, lane);

        const int r4 = lane & 3, colg = lane >> 2;
        const int cg = col0 + colg * 4;
        float bb[4];
#pragma unroll
        for (int j = 0; j < 4; ++j) bb[j] = b2g[cg + j];
#pragma unroll
        for (int p = 0; p < 4; ++p) {
            const int r = row0 + wid * 32 + r4 * 2 + p * 8;
#pragma unroll
            for (int h = 0; h < 2; ++h) {
                const int t = g_s2t[r + h];
                if (t < 0) continue;
                const float g = g_gate1[t];
                float v[4];
#pragma unroll
                for (int j = 0; j < 4; ++j) {
                    float2 u = unpack2(accf[p][j]);
                    v[j] = ((h ? u.y : u.x) + bb[j]) * g;
                }
                *(float4*)(out + (size_t)t * M_DIM + cg) =
                    make_float4(v[0], v[1], v[2], v[3]);
            }
        }
    } else {
        float acct[2][4][4];
#pragma unroll
        for (int mi = 0; mi < 2; ++mi)
#pragma unroll
            for (int ni = 0; ni < 4; ++ni)
#pragma unroll
                for (int k = 0; k < 4; ++k) acct[mi][ni][k] = 0.f;
        const int wid2 = wid - 4;
        mma_loop(sbase, chunks, m, acct, wid2, lane);

        const int wm  = (wid2 & 3) * 32;
        const int wnl = (wid2 >> 2) * 32;
#pragma unroll
        for (int ni = 0; ni < 4; ++ni) {
            const int cg = col0 + FMA_COLS + wnl + ni * 8 + (lane & 3) * 2;
            const float bv0 = b2g[cg], bv1 = b2g[cg + 1];
#pragma unroll
            for (int mi = 0; mi < 2; ++mi)
#pragma unroll
                for (int h = 0; h < 2; ++h) {
                    const int r = row0 + wm + mi * 16 + (lane >> 2) + h * 8;
                    const int t = g_s2t[r];
                    if (t < 0) continue;
                    const float g = g_gate1[t];
                    float2 v;
                    v.x = (acct[mi][ni][h * 2 + 0] + bv0) * g;
                    v.y = (acct[mi][ni][h * 2 + 1] + bv1) * g;
                    *(float2*)(out + (size_t)t * M_DIM + cg) = v;
                }
        }
    }
}

// ---------------- launch ----------------
extern "C" void kernel_launch(void* const* d_in, const int* in_sizes, int n_in,
                              void* d_out, int out_size)
{
    const float* x  = (const float*)d_in[0];
    const float* wg = (const float*)d_in[1];
    const float* w1 = (const float*)d_in[2];
    const float* b1 = (const float*)d_in[3];
    const float* w2 = (const float*)d_in[4];
    const float* b2 = (const float*)d_in[5];
    float* out = (float*)d_out;

    cudaFuncSetAttribute(gemm1_hyb, cudaFuncAttributeMaxDynamicSharedMemorySize,
                         SMEM_BYTES);
    cudaFuncSetAttribute(gemm2_hyb, cudaFuncAttributeMaxDynamicSharedMemorySize,
                         SMEM_BYTES);

    __nv_bfloat16 *w1t_hi, *w1t_lo, *w2t_hi, *w2t_lo;
    cudaGetSymbolAddress((void**)&w1t_hi, g_w1t_hi);
    cudaGetSymbolAddress((void**)&w1t_lo, g_w1t_lo);
    cudaGetSymbolAddress((void**)&w2t_hi, g_w2t_hi);
    cudaGetSymbolAddress((void**)&w2t_lo, g_w2t_lo);

    init_kernel<<<256, 256>>>(out);

    wsplit_kernel<<<dim3((H_DIM / 128) * 3, M_DIM / 32, E_NUM), dim3(32, 8)>>>(
        w1, w1t_hi, w1t_lo, M_DIM, H_DIM);
    wsplit_kernel<<<dim3((M_DIM / 128) * 3, H_DIM / 32, E_NUM), dim3(32, 8)>>>(
        w2, w2t_hi, w2t_lo, H_DIM, M_DIM);

    gate_kernel<<<N_TOK, 256>>>(x, wg);
    sched_kernel<<<1, 256>>>(out, (out_size > N_TOK * M_DIM) ? 1 : 0);
    disp_kernel<<<EC_SLOTS, 256>>>(x);

    gemm1_hyb<<<dim3(H_DIM / 128, EC_SLOTS / 128), NTHREADS, SMEM_BYTES>>>(w1, b1);
    gemm2_hyb<<<dim3(M_DIM / 128, EC_SLOTS / 128), NTHREADS, SMEM_BYTES>>>(w2, b2, out);
}

// round 13
// speedup vs baseline: 3.4223x; 1.6918x over previous
#include <cuda_runtime.h>
#include <cuda_bf16.h>
#include <cstdint>

// ---------------------------------------------------------------------------
// Problem constants
// ---------------------------------------------------------------------------
#define N_TOK    8192
#define M_DIM    2048
#define E_NUM    8
#define H_DIM    8192
#define C_CAP    1024
#define EC_SLOTS 8192

// GEMM tiling: block 128x128, 16 warps (4m x 4n), warp tile 32x32, K-chunk 32
#define KCHUNK   32
#define ROW_STRIDE_B  80                     // 32 bf16 (64B) + 16B pad
#define SPLIT_B  (128 * ROW_STRIDE_B)        // 10240 per split
#define STAGE_B  (4 * SPLIT_B)               // Ah, Al, Bh, Bl = 40960
#define NSTAGE   5
#define SMEM_BYTES (NSTAGE * STAGE_B)        // 204800
#define NTHREADS 512

// ---------------------------------------------------------------------------
// Scratch (device globals; no dynamic allocation allowed)
// ---------------------------------------------------------------------------
__device__ int   g_idx  [N_TOK];
__device__ float g_gate1[N_TOK];
__device__ float g_gates[N_TOK * E_NUM];
__device__ int   g_s2t  [EC_SLOTS];

__device__ __nv_bfloat16 g_disp_hi[(size_t)EC_SLOTS * M_DIM];
__device__ __nv_bfloat16 g_disp_lo[(size_t)EC_SLOTS * M_DIM];
__device__ __nv_bfloat16 g_h_hi   [(size_t)EC_SLOTS * H_DIM];
__device__ __nv_bfloat16 g_h_lo   [(size_t)EC_SLOTS * H_DIM];
// transposed bf16 weight splits: w1T [E][H][M], w2T [E][M][H]  (K contiguous)
__device__ __nv_bfloat16 g_w1t_hi[(size_t)E_NUM * H_DIM * M_DIM];
__device__ __nv_bfloat16 g_w1t_lo[(size_t)E_NUM * H_DIM * M_DIM];
__device__ __nv_bfloat16 g_w2t_hi[(size_t)E_NUM * M_DIM * H_DIM];
__device__ __nv_bfloat16 g_w2t_lo[(size_t)E_NUM * M_DIM * H_DIM];

// ---------------------------------------------------------------------------
// helpers
// ---------------------------------------------------------------------------
__device__ __forceinline__ uint32_t s2u(const void* p) {
    return (uint32_t)__cvta_generic_to_shared(p);
}
__device__ __forceinline__ void cp16(uint32_t s, const void* g) {
    asm volatile("cp.async.cg.shared.global [%0], [%1], 16;" :: "r"(s), "l"(g));
}
__device__ __forceinline__ void ldsm4(uint32_t* r, uint32_t a) {
    asm volatile("ldmatrix.sync.aligned.m8n8.x4.shared.b16 {%0,%1,%2,%3}, [%4];"
                 : "=r"(r[0]), "=r"(r[1]), "=r"(r[2]), "=r"(r[3]) : "r"(a));
}
__device__ __forceinline__ void ldsm2(uint32_t* r, uint32_t a) {
    asm volatile("ldmatrix.sync.aligned.m8n8.x2.shared.b16 {%0,%1}, [%2];"
                 : "=r"(r[0]), "=r"(r[1]) : "r"(a));
}
__device__ __forceinline__ void mmabf16(float* d, const uint32_t* a, const uint32_t* b) {
    asm volatile("mma.sync.aligned.m16n8k16.row.col.f32.bf16.bf16.f32 "
                 "{%0,%1,%2,%3}, {%4,%5,%6,%7}, {%8,%9}, {%0,%1,%2,%3};"
                 : "+f"(d[0]), "+f"(d[1]), "+f"(d[2]), "+f"(d[3])
                 : "r"(a[0]), "r"(a[1]), "r"(a[2]), "r"(a[3]),
                   "r"(b[0]), "r"(b[1]));
}
__device__ __forceinline__ void bsplit(float f, __nv_bfloat16& hi, __nv_bfloat16& lo)
{
    hi = __float2bfloat16(f);
    lo = __float2bfloat16(f - __bfloat162float(hi));
}

// ---------------------------------------------------------------------------
// init: slot table to -1, zero output
// ---------------------------------------------------------------------------
__global__ void init_kernel(float* __restrict__ out)
{
    int tid = blockIdx.x * blockDim.x + threadIdx.x;
    if (tid < EC_SLOTS) g_s2t[tid] = -1;
    float4* o4 = (float4*)out;
    const int n4 = (N_TOK * M_DIM) / 4;
    const int stride = gridDim.x * blockDim.x;
    for (int i = tid; i < n4; i += stride)
        o4[i] = make_float4(0.f, 0.f, 0.f, 0.f);
}

// ---------------------------------------------------------------------------
// gate: exact fp32 routing
// ---------------------------------------------------------------------------
__global__ __launch_bounds__(256) void gate_kernel(
    const float* __restrict__ x, const float* __restrict__ wg)
{
    __shared__ float sx[M_DIM];
    __shared__ float slog[E_NUM];

    const int tok = blockIdx.x;
    const int tid = threadIdx.x;

    const float4* xr = (const float4*)(x + (size_t)tok * M_DIM);
    float4* sx4 = (float4*)sx;
    for (int i = tid; i < M_DIM / 4; i += 256) sx4[i] = xr[i];
    __syncthreads();

    const int wid = tid >> 5, lane = tid & 31;
    const float* __restrict__ w = wg + wid * M_DIM;
    float sum = 0.f;
    for (int m = lane; m < M_DIM; m += 32) sum = fmaf(sx[m], w[m], sum);
#pragma unroll
    for (int o = 16; o; o >>= 1) sum += __shfl_xor_sync(0xffffffffu, sum, o);
    if (lane == 0) slog[wid] = sum;
    __syncthreads();

    if (tid == 0) {
        float mx = slog[0]; int am = 0;
#pragma unroll
        for (int e = 1; e < E_NUM; ++e)
            if (slog[e] > mx) { mx = slog[e]; am = e; }
        float ge[E_NUM], den = 0.f;
#pragma unroll
        for (int e = 0; e < E_NUM; ++e) { ge[e] = expf(slog[e] - mx); den += ge[e]; }
        const float inv = 1.f / den;
#pragma unroll
        for (int e = 0; e < E_NUM; ++e) g_gates[tok * E_NUM + e] = ge[e] * inv;
        g_idx[tok]   = am;
        g_gate1[tok] = ge[am] * inv;
    }
}

// ---------------------------------------------------------------------------
// sched: exact cumsum capacity assignment + l_aux
// ---------------------------------------------------------------------------
__global__ __launch_bounds__(256) void sched_kernel(float* __restrict__ out,
                                                    int write_laux)
{
    __shared__ int   s_ce[E_NUM];
    __shared__ float s_me[E_NUM];

    const int tid = threadIdx.x;
    const int wid = tid >> 5, lane = tid & 31;

    int count = 0;
    for (int base = 0; base < N_TOK; base += 32) {
        const int tok = base + lane;
        const bool mine = (g_idx[tok] == wid);
        const unsigned bal = __ballot_sync(0xffffffffu, mine);
        if (mine) {
            const int loc = count + __popc(bal & ((1u << lane) - 1u));
            if (loc < C_CAP) g_s2t[wid * C_CAP + loc] = tok;
        }
        count += __popc(bal);
    }
    if (lane == 0) s_ce[wid] = count;

    float me = 0.f;
    for (int t = lane; t < N_TOK; t += 32) me += g_gates[t * E_NUM + wid];
#pragma unroll
    for (int o = 16; o; o >>= 1) me += __shfl_xor_sync(0xffffffffu, me, o);
    if (lane == 0) s_me[wid] = me;
    __syncthreads();

    if (tid == 0 && write_laux) {
        float acc = 0.f;
#pragma unroll
        for (int e = 0; e < E_NUM; ++e) acc += s_me[e] * (float)s_ce[e];
        out[(size_t)N_TOK * M_DIM] =
            acc * ((float)E_NUM / ((float)N_TOK * (float)N_TOK));
    }
}

// ---------------------------------------------------------------------------
// disp: gather token rows into slot order, split fp32 -> bf16 hi/lo
// ---------------------------------------------------------------------------
__global__ __launch_bounds__(256) void disp_kernel(const float* __restrict__ x)
{
    const int slot = blockIdx.x;
    const int t = g_s2t[slot];
    const float4* src = (t >= 0) ? (const float4*)(x + (size_t)t * M_DIM) : nullptr;
    __nv_bfloat16* dh = g_disp_hi + (size_t)slot * M_DIM;
    __nv_bfloat16* dl = g_disp_lo + (size_t)slot * M_DIM;
    for (int i = threadIdx.x; i < M_DIM / 4; i += 256) {
        float4 v = src ? src[i] : make_float4(0.f, 0.f, 0.f, 0.f);
        __nv_bfloat16 hh[4], ll[4];
        bsplit(v.x, hh[0], ll[0]); bsplit(v.y, hh[1], ll[1]);
        bsplit(v.z, hh[2], ll[2]); bsplit(v.w, hh[3], ll[3]);
        *(uint2*)(dh + i * 4) = *(uint2*)hh;
        *(uint2*)(dl + i * 4) = *(uint2*)ll;
    }
}

// ---------------------------------------------------------------------------
// wsplit v2: 64x64 tiles, vectorized, amortized index math
//   src [E][R][C] fp32 -> dst [E][C][R] bf16 hi/lo (transpose + split)
// ---------------------------------------------------------------------------
__global__ __launch_bounds__(512) void wsplit_kernel(
    const float* __restrict__ src,
    __nv_bfloat16* __restrict__ dhi,
    __nv_bfloat16* __restrict__ dlo,
    int R, int C)
{
    __shared__ float tile[64][65];
    const int e  = blockIdx.z;
    const int c0 = blockIdx.x * 64;
    const int r0 = blockIdx.y * 64;
    const int tid = threadIdx.x;

    // load 64 rows x 64 cols, float4-vectorized: 1024 float4, 2 per thread
    const float* s = src + (size_t)e * R * C;
#pragma unroll
    for (int i = 0; i < 2; ++i) {
        const int u = tid + i * 512;
        const int row = u >> 4, q = u & 15;
        float4 v = *(const float4*)(s + (size_t)(r0 + row) * C + c0 + q * 4);
        tile[row][q * 4 + 0] = v.x;
        tile[row][q * 4 + 1] = v.y;
        tile[row][q * 4 + 2] = v.z;
        tile[row][q * 4 + 3] = v.w;
    }
    __syncthreads();

    // write transposed: thread -> (col, 8-row group); 8 bf16 = one uint4 per plane
    const int c  = tid >> 3;
    const int rg = tid & 7;
    __nv_bfloat16 hh[8], ll[8];
#pragma unroll
    for (int j = 0; j < 8; ++j)
        bsplit(tile[rg * 8 + j][c], hh[j], ll[j]);
    const size_t o = (size_t)e * C * R + (size_t)(c0 + c) * R + r0 + rg * 8;
    *(uint4*)(dhi + o) = *(uint4*)hh;
    *(uint4*)(dlo + o) = *(uint4*)ll;
}

// ---------------------------------------------------------------------------
// HMMA mainloop: acc += A @ B^T with 3-term bf16 split, 5-stage cp.async pipe
//   16 warps, warp grid 4m x 4n, warp tile 32x32, single barrier per chunk,
//   term-major MMA ordering (independent accumulators between term passes)
// ---------------------------------------------------------------------------
__device__ __forceinline__ void hmma_mainloop(
    const char* __restrict__ Ah, const char* __restrict__ Al,
    const char* __restrict__ Bh, const char* __restrict__ Bl,
    size_t pitch, int chunks, char* smem, float acc[2][4][4])
{
    const int tid  = threadIdx.x;
    const int wid  = tid >> 5, lane = tid & 31;
    const int wm   = (wid & 3) * 32;
    const int wn   = (wid >> 2) * 32;
    const uint32_t sbase = s2u(smem);

    const int lrow = tid >> 2;               // 0..127
    const int lseg = tid & 3;                // 0..3
    const uint32_t lso = lrow * ROW_STRIDE_B + lseg * 16;
    const size_t lgo_base = (size_t)lrow * pitch + lseg * 16;

    auto load_stage = [&](int st, int c) {
        const uint32_t sb = sbase + st * STAGE_B;
        const size_t go = lgo_base + (size_t)c * (KCHUNK * 2);
        cp16(sb + 0 * SPLIT_B + lso, Ah + go);
        cp16(sb + 1 * SPLIT_B + lso, Al + go);
        cp16(sb + 2 * SPLIT_B + lso, Bh + go);
        cp16(sb + 3 * SPLIT_B + lso, Bl + go);
        asm volatile("cp.async.commit_group;");
    };

#pragma unroll
    for (int s = 0; s < NSTAGE - 1; ++s) load_stage(s, s);

    const uint32_t aoff = (uint32_t)((wm + (lane & 15)) * ROW_STRIDE_B
                                     + ((lane >> 4) & 1) * 16);
    const uint32_t boff = (uint32_t)((wn + (lane & 7)) * ROW_STRIDE_B
                                     + ((lane >> 3) & 1) * 16);

    int buf = 0;
#pragma unroll 1
    for (int c = 0; c < chunks; ++c) {
        asm volatile("cp.async.wait_group %0;" :: "n"(NSTAGE - 2) : "memory");
        __syncthreads();

        if (c + NSTAGE - 1 < chunks)
            load_stage((c + NSTAGE - 1) % NSTAGE, c + NSTAGE - 1);

        const uint32_t sb = sbase + buf * STAGE_B;
#pragma unroll
        for (int ks = 0; ks < 2; ++ks) {
            const int kb2 = ks * 32;
            uint32_t ah[2][4], al[2][4], bh[4][2], bl[4][2];
#pragma unroll
            for (int mi = 0; mi < 2; ++mi) {
                const uint32_t ad = sb + aoff + kb2 + mi * 16 * ROW_STRIDE_B;
                ldsm4(ah[mi], ad);
                ldsm4(al[mi], ad + SPLIT_B);
            }
#pragma unroll
            for (int ni = 0; ni < 4; ++ni) {
                const uint32_t bd = sb + 2 * SPLIT_B + boff + kb2
                                    + ni * 8 * ROW_STRIDE_B;
                ldsm2(bh[ni], bd);
                ldsm2(bl[ni], bd + SPLIT_B);
            }
#pragma unroll
            for (int mi = 0; mi < 2; ++mi)
#pragma unroll
                for (int ni = 0; ni < 4; ++ni)
                    mmabf16(acc[mi][ni], ah[mi], bh[ni]);
#pragma unroll
            for (int mi = 0; mi < 2; ++mi)
#pragma unroll
                for (int ni = 0; ni < 4; ++ni)
                    mmabf16(acc[mi][ni], al[mi], bh[ni]);
#pragma unroll
            for (int mi = 0; mi < 2; ++mi)
#pragma unroll
                for (int ni = 0; ni < 4; ++ni)
                    mmabf16(acc[mi][ni], ah[mi], bl[ni]);
        }
        buf = (buf + 1 == NSTAGE) ? 0 : buf + 1;
    }
}

// ---------------------------------------------------------------------------
// GEMM1: h[slot] = relu( disp[slot] @ w1[e]^T(cols) + b1[e] ) -> split hi/lo
// ---------------------------------------------------------------------------
__global__ __launch_bounds__(NTHREADS, 1) void gemm1_mma(const float* __restrict__ b1)
{
    extern __shared__ char smem[];
    const int tid = threadIdx.x;
    const int wid = tid >> 5, lane = tid & 31;
    const int row0 = blockIdx.y * 128;
    const int col0 = blockIdx.x * 128;
    const int e    = row0 >> 10;

    float acc[2][4][4];
#pragma unroll
    for (int mi = 0; mi < 2; ++mi)
#pragma unroll
        for (int ni = 0; ni < 4; ++ni)
#pragma unroll
            for (int k = 0; k < 4; ++k) acc[mi][ni][k] = 0.f;

    hmma_mainloop(
        (const char*)(g_disp_hi + (size_t)row0 * M_DIM),
        (const char*)(g_disp_lo + (size_t)row0 * M_DIM),
        (const char*)(g_w1t_hi + (size_t)e * H_DIM * M_DIM + (size_t)col0 * M_DIM),
        (const char*)(g_w1t_lo + (size_t)e * H_DIM * M_DIM + (size_t)col0 * M_DIM),
        (size_t)M_DIM * 2, M_DIM / KCHUNK, smem, acc);

    const int wm = (wid & 3) * 32;
    const int wn = (wid >> 2) * 32;
    const float* b1g = b1 + (size_t)e * H_DIM;

#pragma unroll
    for (int ni = 0; ni < 4; ++ni) {
        const int cg = col0 + wn + ni * 8 + (lane & 3) * 2;
        const float bv0 = b1g[cg], bv1 = b1g[cg + 1];
#pragma unroll
        for (int mi = 0; mi < 2; ++mi)
#pragma unroll
            for (int h = 0; h < 2; ++h) {
                const int rg = row0 + wm + mi * 16 + (lane >> 2) + h * 8;
                float v0 = fmaxf(acc[mi][ni][h * 2 + 0] + bv0, 0.f);
                float v1 = fmaxf(acc[mi][ni][h * 2 + 1] + bv1, 0.f);
                __nv_bfloat16 h0, l0, h1, l1;
                bsplit(v0, h0, l0);
                bsplit(v1, h1, l1);
                *(__nv_bfloat162*)(g_h_hi + (size_t)rg * H_DIM + cg) =
                    __nv_bfloat162(h0, h1);
                *(__nv_bfloat162*)(g_h_lo + (size_t)rg * H_DIM + cg) =
                    __nv_bfloat162(l0, l1);
            }
    }
}

// ---------------------------------------------------------------------------
// GEMM2: out[token(slot)] = gate1 * ( h[slot] @ w2[e]^T(cols) + b2[e] )
// ---------------------------------------------------------------------------
__global__ __launch_bounds__(NTHREADS, 1) void gemm2_mma(const float* __restrict__ b2,
                                                         float* __restrict__ out)
{
    extern __shared__ char smem[];
    const int tid = threadIdx.x;
    const int wid = tid >> 5, lane = tid & 31;
    const int row0 = blockIdx.y * 128;
    const int col0 = blockIdx.x * 128;
    const int e    = row0 >> 10;

    float acc[2][4][4];
#pragma unroll
    for (int mi = 0; mi < 2; ++mi)
#pragma unroll
        for (int ni = 0; ni < 4; ++ni)
#pragma unroll
            for (int k = 0; k < 4; ++k) acc[mi][ni][k] = 0.f;

    hmma_mainloop(
        (const char*)(g_h_hi + (size_t)row0 * H_DIM),
        (const char*)(g_h_lo + (size_t)row0 * H_DIM),
        (const char*)(g_w2t_hi + (size_t)e * M_DIM * H_DIM + (size_t)col0 * H_DIM),
        (const char*)(g_w2t_lo + (size_t)e * M_DIM * H_DIM + (size_t)col0 * H_DIM),
        (size_t)H_DIM * 2, H_DIM / KCHUNK, smem, acc);

    const int wm = (wid & 3) * 32;
    const int wn = (wid >> 2) * 32;
    const float* b2g = b2 + (size_t)e * M_DIM;

#pragma unroll
    for (int ni = 0; ni < 4; ++ni) {
        const int cg = col0 + wn + ni * 8 + (lane & 3) * 2;
        const float bv0 = b2g[cg], bv1 = b2g[cg + 1];
#pragma unroll
        for (int mi = 0; mi < 2; ++mi)
#pragma unroll
            for (int h = 0; h < 2; ++h) {
                const int rg = row0 + wm + mi * 16 + (lane >> 2) + h * 8;
                const int t = g_s2t[rg];
                if (t < 0) continue;
                const float g = g_gate1[t];
                float2 v;
                v.x = (acc[mi][ni][h * 2 + 0] + bv0) * g;
                v.y = (acc[mi][ni][h * 2 + 1] + bv1) * g;
                *(float2*)(out + (size_t)t * M_DIM + cg) = v;
            }
    }
}

// ---------------------------------------------------------------------------
// launch
// ---------------------------------------------------------------------------
extern "C" void kernel_launch(void* const* d_in, const int* in_sizes, int n_in,
                              void* d_out, int out_size)
{
    const float* x  = (const float*)d_in[0];
    const float* wg = (const float*)d_in[1];
    const float* w1 = (const float*)d_in[2];
    const float* b1 = (const float*)d_in[3];
    const float* w2 = (const float*)d_in[4];
    const float* b2 = (const float*)d_in[5];
    float* out = (float*)d_out;

    cudaFuncSetAttribute(gemm1_mma, cudaFuncAttributeMaxDynamicSharedMemorySize,
                         SMEM_BYTES);
    cudaFuncSetAttribute(gemm2_mma, cudaFuncAttributeMaxDynamicSharedMemorySize,
                         SMEM_BYTES);

    __nv_bfloat16 *w1t_hi, *w1t_lo, *w2t_hi, *w2t_lo;
    cudaGetSymbolAddress((void**)&w1t_hi, g_w1t_hi);
    cudaGetSymbolAddress((void**)&w1t_lo, g_w1t_lo);
    cudaGetSymbolAddress((void**)&w2t_hi, g_w2t_hi);
    cudaGetSymbolAddress((void**)&w2t_lo, g_w2t_lo);

    init_kernel<<<512, 256>>>(out);

    // wsplit v2: 64x64 tiles  (w1: R=M, C=H ; w2: R=H, C=M)
    wsplit_kernel<<<dim3(H_DIM / 64, M_DIM / 64, E_NUM), 512>>>(
        w1, w1t_hi, w1t_lo, M_DIM, H_DIM);
    wsplit_kernel<<<dim3(M_DIM / 64, H_DIM / 64, E_NUM), 512>>>(
        w2, w2t_hi, w2t_lo, H_DIM, M_DIM);

    gate_kernel<<<N_TOK, 256>>>(x, wg);
    sched_kernel<<<1, 256>>>(out, (out_size > N_TOK * M_DIM) ? 1 : 0);
    disp_kernel<<<EC_SLOTS, 256>>>(x);

    gemm1_mma<<<dim3(H_DIM / 128, EC_SLOTS / 128), NTHREADS, SMEM_BYTES>>>(b1);
    gemm2_mma<<<dim3(M_DIM / 128, EC_SLOTS / 128), NTHREADS, SMEM_BYTES>>>(b2, out);
}